// round 3
// baseline (speedup 1.0000x reference)
#include <cuda_runtime.h>
#include <cuda_bf16.h>

// Problem constants
#define BB 16
#define SS 1024
#define DD 512
#define HH 8
#define DKK 64
#define MROWS (BB*SS)          // 16384
#define ELEMS (MROWS*DD)       // 8388608

// ---------------- scratch buffers (no allocation allowed) ----------------
__device__ float g_Qh[ELEMS];   // [B,H,S,DK]
__device__ float g_Kh[ELEMS];
__device__ float g_Vh[ELEMS];
__device__ float g_ctx[ELEMS];  // [B*S, D]
__device__ float g_att[ELEMS];  // ctx @ W_o
__device__ float g_out1[ELEMS]; // after first LN
__device__ float g_hid[ELEMS];  // gelu(out1 @ lin1 + b1)
__device__ float g_ffn[ELEMS];  // hid @ lin2 + b2

// ---------------- helpers ----------------
__device__ __forceinline__ float gelu_tanh_f(float x) {
    float x3 = x * x * x;
    return 0.5f * x * (1.0f + tanhf(0.7978845608028654f * (x + 0.044715f * x3)));
}

// ---------------- SGEMM 128x128x8, 256 threads, 8x8 microtile ----------------
#define GBM 128
#define GBN 128
#define GBK 8
#define GTM 8
#define GTN 8

enum { EPI_QKV = 0, EPI_PLAIN = 1, EPI_BIAS = 2, EPI_BIASGELU = 3 };

template <int EPI>
__global__ __launch_bounds__(256) void sgemm_kernel(
    const float* __restrict__ A,     // [M,K] row-major
    const float* __restrict__ Bw,    // [K,N] row-major
    const float* __restrict__ bias,  // [N] or null
    float* __restrict__ C,
    int M, int N, int K, float scale)
{
    __shared__ float As[GBK][GBM];
    __shared__ float Bs[GBK][GBN];

    const int tid = threadIdx.x;
    const int bcol = blockIdx.x;
    const int brow = blockIdx.y;

    const int threadCol = tid % (GBN / GTN);  // 0..15
    const int threadRow = tid / (GBN / GTN);  // 0..15

    const int innerRowA = tid >> 1;           // 0..127
    const int innerColA = (tid & 1) << 2;     // 0 or 4
    const int innerRowB = tid >> 5;           // 0..7
    const int innerColB = (tid & 31) << 2;    // 0..124

    const float* Aptr = A + (long)(brow * GBM) * K;
    const float* Bptr = Bw + bcol * GBN;

    float acc[GTM][GTN] = {};

    for (int k0 = 0; k0 < K; k0 += GBK) {
        float4 a = *(const float4*)(Aptr + (long)innerRowA * K + k0 + innerColA);
        As[innerColA + 0][innerRowA] = a.x;
        As[innerColA + 1][innerRowA] = a.y;
        As[innerColA + 2][innerRowA] = a.z;
        As[innerColA + 3][innerRowA] = a.w;
        *(float4*)&Bs[innerRowB][innerColB] =
            *(const float4*)(Bptr + (long)(k0 + innerRowB) * N + innerColB);
        __syncthreads();

        #pragma unroll
        for (int k = 0; k < GBK; k++) {
            float4 m0 = *(const float4*)&As[k][threadRow * GTM];
            float4 m1 = *(const float4*)&As[k][threadRow * GTM + 4];
            float4 n0 = *(const float4*)&Bs[k][threadCol * GTN];
            float4 n1 = *(const float4*)&Bs[k][threadCol * GTN + 4];
            float rm[GTM] = {m0.x, m0.y, m0.z, m0.w, m1.x, m1.y, m1.z, m1.w};
            float rn[GTN] = {n0.x, n0.y, n0.z, n0.w, n1.x, n1.y, n1.z, n1.w};
            #pragma unroll
            for (int i = 0; i < GTM; i++)
                #pragma unroll
                for (int j = 0; j < GTN; j++)
                    acc[i][j] += rm[i] * rn[j];
        }
        __syncthreads();
    }

    // epilogue
    #pragma unroll
    for (int i = 0; i < GTM; i++) {
        int m = brow * GBM + threadRow * GTM + i;
        #pragma unroll
        for (int j = 0; j < GTN; j++) {
            int n = bcol * GBN + threadCol * GTN + j;
            float v = acc[i][j];
            if (EPI == EPI_QKV) {
                // m = b*S + s ; n = h*DK + dk ; out layout [B,H,S,DK]
                int b = m >> 10, s = m & 1023;
                int h = n >> 6, dk = n & 63;
                C[((((long)b * HH + h) << 10) + s) * DKK + dk] = v * scale;
            } else if (EPI == EPI_PLAIN) {
                C[(long)m * N + n] = v;
            } else if (EPI == EPI_BIAS) {
                C[(long)m * N + n] = v + bias[n];
            } else { // EPI_BIASGELU
                C[(long)m * N + n] = gelu_tanh_f(v + bias[n]);
            }
        }
    }
}

// ---------------- Flash attention (fp32, causal + pad mask) ----------------
// One block = 128 query rows of one (b,h); thread t owns query row qt*128+t.
// Q and O accumulators in registers; 32-key smem tiles; online softmax.
__global__ __launch_bounds__(128) void flash_kernel(
    const unsigned char* __restrict__ mask, float* __restrict__ ctx)
{
    const int t = threadIdx.x;       // 0..127
    const int qt = blockIdx.x;       // 0..7
    const int h = blockIdx.y;        // 0..7
    const int b = blockIdx.z;        // 0..15
    const int q = qt * 128 + t;
    const long base = ((long)(b * HH + h)) << 16;  // *S*DK = *65536

    __shared__ float Ks[32][64];
    __shared__ float Vs[32][64];
    __shared__ unsigned char Ms[32];

    float Qreg[64];
    #pragma unroll
    for (int d = 0; d < 64; d += 4) {
        float4 v = *(const float4*)&g_Qh[base + (long)q * 64 + d];
        Qreg[d] = v.x; Qreg[d + 1] = v.y; Qreg[d + 2] = v.z; Qreg[d + 3] = v.w;
    }

    float Oreg[64] = {};
    float mrun = -1e30f, lrun = 0.0f;

    const int ntiles = (qt + 1) * 4;  // key tiles of 32, covering keys <= qmax
    for (int kt = 0; kt < ntiles; kt++) {
        const int k0 = kt * 32;
        __syncthreads();
        #pragma unroll
        for (int i = 0; i < 4; i++) {
            int li = t + 128 * i;          // 0..511
            int r = li >> 4;               // 0..31
            int c = (li & 15) << 2;        // 0..60
            *(float4*)&Ks[r][c] = *(const float4*)&g_Kh[base + (long)(k0 + r) * 64 + c];
            *(float4*)&Vs[r][c] = *(const float4*)&g_Vh[base + (long)(k0 + r) * 64 + c];
        }
        if (t < 32) Ms[t] = mask[b * SS + k0 + t];
        __syncthreads();

        float Sreg[32];
        float tmax = -1e30f;
        #pragma unroll
        for (int kk = 0; kk < 32; kk++) {
            float s = 0.0f;
            #pragma unroll
            for (int d4 = 0; d4 < 16; d4++) {
                float4 kv = *(const float4*)&Ks[kk][d4 * 4];
                s += Qreg[d4 * 4 + 0] * kv.x;
                s += Qreg[d4 * 4 + 1] * kv.y;
                s += Qreg[d4 * 4 + 2] * kv.z;
                s += Qreg[d4 * 4 + 3] * kv.w;
            }
            int kg = k0 + kk;
            bool valid = (kg <= q) && (Ms[kk] == 0);
            s = valid ? s : -1e30f;
            Sreg[kk] = s;
            tmax = fmaxf(tmax, s);
        }

        float mnew = fmaxf(mrun, tmax);
        float corr = __expf(mrun - mnew);
        lrun *= corr;
        #pragma unroll
        for (int d = 0; d < 64; d++) Oreg[d] *= corr;

        #pragma unroll
        for (int kk = 0; kk < 32; kk++) {
            float p = __expf(Sreg[kk] - mnew);
            lrun += p;
            #pragma unroll
            for (int d4 = 0; d4 < 16; d4++) {
                float4 vv = *(const float4*)&Vs[kk][d4 * 4];
                Oreg[d4 * 4 + 0] += p * vv.x;
                Oreg[d4 * 4 + 1] += p * vv.y;
                Oreg[d4 * 4 + 2] += p * vv.z;
                Oreg[d4 * 4 + 3] += p * vv.w;
            }
        }
        mrun = mnew;
    }

    const float inv = 1.0f / lrun;
    // ctx layout: [b*S+q, D], columns h*64 + d
    float* dst = &ctx[((long)(b * SS + q)) * DD + h * DKK];
    #pragma unroll
    for (int d = 0; d < 64; d += 4) {
        float4 v;
        v.x = Oreg[d] * inv; v.y = Oreg[d + 1] * inv;
        v.z = Oreg[d + 2] * inv; v.w = Oreg[d + 3] * inv;
        *(float4*)&dst[d] = v;
    }
}

// ---------------- residual + LayerNorm (row of 512, 512 threads) ----------------
__global__ __launch_bounds__(512) void ln_kernel(
    const float* __restrict__ X, const float* __restrict__ R,
    const float* __restrict__ g, const float* __restrict__ bta,
    float* __restrict__ out)
{
    const int row = blockIdx.x;
    const int t = threadIdx.x;
    const long off = (long)row * DD + t;
    const float xv = X[off] + R[off];

    __shared__ float red[16];
    __shared__ float sh_mu, sh_rstd;

    float s = xv;
    #pragma unroll
    for (int o = 16; o; o >>= 1) s += __shfl_xor_sync(0xffffffffu, s, o);
    if ((t & 31) == 0) red[t >> 5] = s;
    __syncthreads();
    if (t < 16) {
        float v = red[t];
        #pragma unroll
        for (int o = 8; o; o >>= 1) v += __shfl_xor_sync(0x0000ffffu, v, o);
        if (t == 0) sh_mu = v * (1.0f / DD);
    }
    __syncthreads();
    const float mu = sh_mu;
    const float d = xv - mu;

    s = d * d;
    #pragma unroll
    for (int o = 16; o; o >>= 1) s += __shfl_xor_sync(0xffffffffu, s, o);
    __syncthreads();  // red reuse safety
    if ((t & 31) == 0) red[t >> 5] = s;
    __syncthreads();
    if (t < 16) {
        float v = red[t];
        #pragma unroll
        for (int o = 8; o; o >>= 1) v += __shfl_xor_sync(0x0000ffffu, v, o);
        if (t == 0) sh_rstd = rsqrtf(v * (1.0f / DD) + 1e-5f);
    }
    __syncthreads();

    out[off] = d * sh_rstd * g[t] + bta[t];
}

// ---------------- launch ----------------
extern "C" void kernel_launch(void* const* d_in, const int* in_sizes, int n_in,
                              void* d_out, int out_size)
{
    const float* Q      = (const float*)d_in[0];
    const float* K      = (const float*)d_in[1];
    const float* V      = (const float*)d_in[2];
    const unsigned char* mask = (const unsigned char*)d_in[3];
    const float* W_q    = (const float*)d_in[4];
    const float* W_k    = (const float*)d_in[5];
    const float* W_v    = (const float*)d_in[6];
    const float* W_o    = (const float*)d_in[7];
    const float* lin1_w = (const float*)d_in[8];
    const float* lin1_b = (const float*)d_in[9];
    const float* lin2_w = (const float*)d_in[10];
    const float* lin2_b = (const float*)d_in[11];
    const float* ln_g   = (const float*)d_in[12];
    const float* ln_b   = (const float*)d_in[13];
    float* out = (float*)d_out;

    float *Qh, *Kh, *Vh, *ctx, *att, *out1, *hid, *ffn;
    cudaGetSymbolAddress((void**)&Qh,  g_Qh);
    cudaGetSymbolAddress((void**)&Kh,  g_Kh);
    cudaGetSymbolAddress((void**)&Vh,  g_Vh);
    cudaGetSymbolAddress((void**)&ctx, g_ctx);
    cudaGetSymbolAddress((void**)&att, g_att);
    cudaGetSymbolAddress((void**)&out1, g_out1);
    cudaGetSymbolAddress((void**)&hid, g_hid);
    cudaGetSymbolAddress((void**)&ffn, g_ffn);

    dim3 ggrid(DD / GBN, MROWS / GBM);   // (4, 128)
    dim3 gblk(256);
    const float invT = 1.0f / (8.0f + 1e-6f);  // 1/(sqrt(DK)+eps), folded into Q proj

    // QKV projections (head-layout epilogue; Q pre-scaled)
    sgemm_kernel<EPI_QKV><<<ggrid, gblk>>>(Q, W_q, nullptr, Qh, MROWS, DD, DD, invT);
    sgemm_kernel<EPI_QKV><<<ggrid, gblk>>>(K, W_k, nullptr, Kh, MROWS, DD, DD, 1.0f);
    sgemm_kernel<EPI_QKV><<<ggrid, gblk>>>(V, W_v, nullptr, Vh, MROWS, DD, DD, 1.0f);

    // attention
    flash_kernel<<<dim3(SS / 128, HH, BB), 128>>>(mask, ctx);

    // output projection + residual LN
    sgemm_kernel<EPI_PLAIN><<<ggrid, gblk>>>(ctx, W_o, nullptr, att, MROWS, DD, DD, 1.0f);
    ln_kernel<<<MROWS, DD>>>(att, Q, ln_g, ln_b, out1);

    // FFN
    sgemm_kernel<EPI_BIASGELU><<<ggrid, gblk>>>(out1, lin1_w, lin1_b, hid, MROWS, DD, DD, 1.0f);
    sgemm_kernel<EPI_BIAS><<<ggrid, gblk>>>(hid, lin2_w, lin2_b, ffn, MROWS, DD, DD, 1.0f);
    ln_kernel<<<MROWS, DD>>>(ffn, out1, ln_g, ln_b, out);
}

// round 4
// speedup vs baseline: 1.2520x; 1.2520x over previous
#include <cuda_runtime.h>
#include <cuda_bf16.h>
#include <cstdint>

// Problem constants
#define BB 16
#define SS 1024
#define DD 512
#define HH 8
#define DKK 64
#define MROWS (BB*SS)          // 16384
#define ELEMS (MROWS*DD)       // 8388608

// ---------------- scratch buffers (no allocation allowed) ----------------
__device__ float g_Qh[ELEMS];   // [B,H,S,DK]
__device__ float g_Kh[ELEMS];
__device__ float g_Vh[ELEMS];
__device__ float g_ctx[ELEMS];  // [B*S, D]
__device__ float g_att[ELEMS];  // ctx @ W_o
__device__ float g_out1[ELEMS]; // after first LN
__device__ float g_hid[ELEMS];  // gelu(out1 @ lin1 + b1)
__device__ float g_ffn[ELEMS];  // hid @ lin2 + b2

// ---------------- helpers ----------------
__device__ __forceinline__ float gelu_tanh_f(float x) {
    float x3 = x * x * x;
    return 0.5f * x * (1.0f + tanhf(0.7978845608028654f * (x + 0.044715f * x3)));
}

__device__ __forceinline__ float to_tf32f(float x) {
    uint32_t u;
    asm("cvt.rna.tf32.f32 %0, %1;" : "=r"(u) : "f"(x));
    return __uint_as_float(u);
}

__device__ __forceinline__ void mma_tf32(
    float& d0, float& d1, float& d2, float& d3,
    uint32_t a0, uint32_t a1, uint32_t a2, uint32_t a3,
    uint32_t b0, uint32_t b1)
{
    asm volatile(
        "mma.sync.aligned.m16n8k8.row.col.f32.tf32.tf32.f32 "
        "{%0,%1,%2,%3}, {%4,%5,%6,%7}, {%8,%9}, {%0,%1,%2,%3};\n"
        : "+f"(d0), "+f"(d1), "+f"(d2), "+f"(d3)
        : "r"(a0), "r"(a1), "r"(a2), "r"(a3), "r"(b0), "r"(b1));
}

// ---------------- TF32 tensor-core GEMM 128x128x32, 256 threads ----------------
// Block tile 128x128, BK=32, 8 warps in 4(m) x 2(n), warp tile 32x64.
// Per warp: 2 (m) x 8 (n) mma tiles of m16n8k8, 4 k-steps per BK.
#define TBM 128
#define TBN 128
#define TBK 32

enum { EPI_QKV = 0, EPI_PLAIN = 1, EPI_BIAS = 2, EPI_BIASGELU = 3 };

template <int EPI>
__global__ __launch_bounds__(256) void mma_gemm_kernel(
    const float* __restrict__ A,     // [M,K] row-major
    const float* __restrict__ Bw,    // [K,N] row-major
    const float* __restrict__ bias,  // [N] or null
    float* __restrict__ C,
    int M, int N, int K, float scale)
{
    __shared__ __align__(16) float As[TBK][TBM + 1];  // [k][m], pad->129
    __shared__ __align__(16) float Bs[TBK][TBN + 4];  // [k][n], pad->132

    const int tid  = threadIdx.x;
    const int lane = tid & 31;
    const int warp = tid >> 5;      // 0..7
    const int warpM = warp >> 1;    // 0..3
    const int warpN = warp & 1;     // 0..1
    const int g  = lane >> 2;       // 0..7  (groupID)
    const int tg = lane & 3;        // 0..3  (thread in group)

    const int mBase = warpM * 32;
    const int nBase = warpN * 64;

    const long rowBlock = (long)blockIdx.y * TBM;
    const int  colBlock = blockIdx.x * TBN;

    // global load mapping
    const int lrow  = tid >> 3;          // 0..31
    const int lcol4 = (tid & 7) << 2;    // 0,4,...,28   (A cols; B col4 base)

    float acc[2][8][4];
    #pragma unroll
    for (int i = 0; i < 2; i++)
        #pragma unroll
        for (int j = 0; j < 8; j++)
            #pragma unroll
            for (int c = 0; c < 4; c++) acc[i][j][c] = 0.0f;

    for (int kt = 0; kt < K; kt += TBK) {
        // ---- load A tile: 128 rows x 32 cols ----
        #pragma unroll
        for (int i = 0; i < 4; i++) {
            int r = lrow + 32 * i;
            float4 v = *(const float4*)(A + (rowBlock + r) * K + kt + lcol4);
            As[lcol4 + 0][r] = to_tf32f(v.x);
            As[lcol4 + 1][r] = to_tf32f(v.y);
            As[lcol4 + 2][r] = to_tf32f(v.z);
            As[lcol4 + 3][r] = to_tf32f(v.w);
        }
        // ---- load B tile: 32 rows x 128 cols ----
        {
            int r = lrow;                         // each thread: one k-row
            const float* src = Bw + (long)(kt + r) * N + colBlock;
            #pragma unroll
            for (int i = 0; i < 4; i++) {
                int c = ((tid & 7) + 8 * i) << 2;  // 0..124
                float4 v = *(const float4*)(src + c);
                float4 w;
                w.x = to_tf32f(v.x); w.y = to_tf32f(v.y);
                w.z = to_tf32f(v.z); w.w = to_tf32f(v.w);
                *(float4*)&Bs[r][c] = w;
            }
        }
        __syncthreads();

        #pragma unroll
        for (int kk = 0; kk < 4; kk++) {
            const int k0 = kk * 8;
            uint32_t af[2][4];
            #pragma unroll
            for (int mi = 0; mi < 2; mi++) {
                int m = mBase + mi * 16 + g;
                af[mi][0] = __float_as_uint(As[k0 + tg][m]);
                af[mi][1] = __float_as_uint(As[k0 + tg][m + 8]);
                af[mi][2] = __float_as_uint(As[k0 + tg + 4][m]);
                af[mi][3] = __float_as_uint(As[k0 + tg + 4][m + 8]);
            }
            uint32_t bf[8][2];
            #pragma unroll
            for (int ni = 0; ni < 8; ni++) {
                int n = nBase + ni * 8 + g;
                bf[ni][0] = __float_as_uint(Bs[k0 + tg][n]);
                bf[ni][1] = __float_as_uint(Bs[k0 + tg + 4][n]);
            }
            #pragma unroll
            for (int mi = 0; mi < 2; mi++)
                #pragma unroll
                for (int ni = 0; ni < 8; ni++)
                    mma_tf32(acc[mi][ni][0], acc[mi][ni][1], acc[mi][ni][2], acc[mi][ni][3],
                             af[mi][0], af[mi][1], af[mi][2], af[mi][3],
                             bf[ni][0], bf[ni][1]);
        }
        __syncthreads();
    }

    // ---- epilogue ----
    #pragma unroll
    for (int mi = 0; mi < 2; mi++) {
        #pragma unroll
        for (int ri = 0; ri < 2; ri++) {         // row g or g+8
            int m = (int)rowBlock + mBase + mi * 16 + g + ri * 8;
            #pragma unroll
            for (int ni = 0; ni < 8; ni++) {
                int n = colBlock + nBase + ni * 8 + tg * 2;
                float v0 = acc[mi][ni][ri * 2 + 0];
                float v1 = acc[mi][ni][ri * 2 + 1];
                if (EPI == EPI_QKV) {
                    int b = m >> 10, s = m & 1023;
                    int h = n >> 6, dk = n & 63;
                    float2 o; o.x = v0 * scale; o.y = v1 * scale;
                    *(float2*)&C[(((((long)b * HH + h) << 10) + s) << 6) + dk] = o;
                } else if (EPI == EPI_PLAIN) {
                    float2 o; o.x = v0; o.y = v1;
                    *(float2*)&C[(long)m * N + n] = o;
                } else if (EPI == EPI_BIAS) {
                    float2 o; o.x = v0 + bias[n]; o.y = v1 + bias[n + 1];
                    *(float2*)&C[(long)m * N + n] = o;
                } else {  // EPI_BIASGELU
                    float2 o;
                    o.x = gelu_tanh_f(v0 + bias[n]);
                    o.y = gelu_tanh_f(v1 + bias[n + 1]);
                    *(float2*)&C[(long)m * N + n] = o;
                }
            }
        }
    }
}

// ---------------- Flash attention (fp32, causal + pad mask) ----------------
// 256 threads = 128 query rows, 2 threads per row (each owns 32 of 64 dims).
// QK partial dot combined via shfl_xor(1). Online softmax state duplicated per pair.
__global__ __launch_bounds__(256, 2) void flash_kernel(
    const unsigned char* __restrict__ mask, float* __restrict__ ctx)
{
    const int t = threadIdx.x;        // 0..255
    const int half = t & 1;
    const int r = t >> 1;             // 0..127
    const int qt = blockIdx.x;        // 0..7
    const int h = blockIdx.y;         // 0..7
    const int b = blockIdx.z;         // 0..15
    const int q = qt * 128 + r;
    const long base = ((long)(b * HH + h)) << 16;  // *S*DK
    const int doff = half * 32;

    __shared__ float Ks[32][64];
    __shared__ float Vs[32][64];
    __shared__ unsigned char Ms[32];

    float Qreg[32];
    #pragma unroll
    for (int d = 0; d < 32; d += 4) {
        float4 v = *(const float4*)&g_Qh[base + (long)q * 64 + doff + d];
        Qreg[d] = v.x; Qreg[d + 1] = v.y; Qreg[d + 2] = v.z; Qreg[d + 3] = v.w;
    }

    float Oreg[32] = {};
    float mrun = -1e30f, lrun = 0.0f;

    const int ntiles = (qt + 1) * 4;
    for (int kt = 0; kt < ntiles; kt++) {
        const int k0 = kt * 32;
        __syncthreads();
        #pragma unroll
        for (int i = 0; i < 2; i++) {
            int li = t + 256 * i;          // 0..511
            int rr = li >> 4;              // 0..31
            int cc = (li & 15) << 2;       // 0..60
            *(float4*)&Ks[rr][cc] = *(const float4*)&g_Kh[base + (long)(k0 + rr) * 64 + cc];
            *(float4*)&Vs[rr][cc] = *(const float4*)&g_Vh[base + (long)(k0 + rr) * 64 + cc];
        }
        if (t < 32) Ms[t] = mask[b * SS + k0 + t];
        __syncthreads();

        float Sreg[32];
        float tmax = -1e30f;
        #pragma unroll
        for (int kk = 0; kk < 32; kk++) {
            float s = 0.0f;
            #pragma unroll
            for (int d4 = 0; d4 < 8; d4++) {
                float4 kv = *(const float4*)&Ks[kk][doff + d4 * 4];
                s += Qreg[d4 * 4 + 0] * kv.x;
                s += Qreg[d4 * 4 + 1] * kv.y;
                s += Qreg[d4 * 4 + 2] * kv.z;
                s += Qreg[d4 * 4 + 3] * kv.w;
            }
            s += __shfl_xor_sync(0xffffffffu, s, 1);   // combine halves
            int kg = k0 + kk;
            bool valid = (kg <= q) && (Ms[kk] == 0);
            s = valid ? s : -1e30f;
            Sreg[kk] = s;
            tmax = fmaxf(tmax, s);
        }

        float mnew = fmaxf(mrun, tmax);
        float corr = __expf(mrun - mnew);
        lrun *= corr;
        #pragma unroll
        for (int d = 0; d < 32; d++) Oreg[d] *= corr;

        #pragma unroll
        for (int kk = 0; kk < 32; kk++) {
            float p = __expf(Sreg[kk] - mnew);
            lrun += p;
            #pragma unroll
            for (int d4 = 0; d4 < 8; d4++) {
                float4 vv = *(const float4*)&Vs[kk][doff + d4 * 4];
                Oreg[d4 * 4 + 0] += p * vv.x;
                Oreg[d4 * 4 + 1] += p * vv.y;
                Oreg[d4 * 4 + 2] += p * vv.z;
                Oreg[d4 * 4 + 3] += p * vv.w;
            }
        }
        mrun = mnew;
    }

    const float inv = 1.0f / lrun;
    float* dst = &ctx[((long)(b * SS + q)) * DD + h * DKK + doff];
    #pragma unroll
    for (int d = 0; d < 32; d += 4) {
        float4 v;
        v.x = Oreg[d] * inv; v.y = Oreg[d + 1] * inv;
        v.z = Oreg[d + 2] * inv; v.w = Oreg[d + 3] * inv;
        *(float4*)&dst[d] = v;
    }
}

// ---------------- residual + LayerNorm (row of 512, 512 threads) ----------------
__global__ __launch_bounds__(512) void ln_kernel(
    const float* __restrict__ X, const float* __restrict__ R,
    const float* __restrict__ g, const float* __restrict__ bta,
    float* __restrict__ out)
{
    const int row = blockIdx.x;
    const int t = threadIdx.x;
    const long off = (long)row * DD + t;
    const float xv = X[off] + R[off];

    __shared__ float red[16];
    __shared__ float sh_mu, sh_rstd;

    float s = xv;
    #pragma unroll
    for (int o = 16; o; o >>= 1) s += __shfl_xor_sync(0xffffffffu, s, o);
    if ((t & 31) == 0) red[t >> 5] = s;
    __syncthreads();
    if (t < 16) {
        float v = red[t];
        #pragma unroll
        for (int o = 8; o; o >>= 1) v += __shfl_xor_sync(0x0000ffffu, v, o);
        if (t == 0) sh_mu = v * (1.0f / DD);
    }
    __syncthreads();
    const float mu = sh_mu;
    const float d = xv - mu;

    s = d * d;
    #pragma unroll
    for (int o = 16; o; o >>= 1) s += __shfl_xor_sync(0xffffffffu, s, o);
    __syncthreads();
    if ((t & 31) == 0) red[t >> 5] = s;
    __syncthreads();
    if (t < 16) {
        float v = red[t];
        #pragma unroll
        for (int o = 8; o; o >>= 1) v += __shfl_xor_sync(0x0000ffffu, v, o);
        if (t == 0) sh_rstd = rsqrtf(v * (1.0f / DD) + 1e-5f);
    }
    __syncthreads();

    out[off] = d * sh_rstd * g[t] + bta[t];
}

// ---------------- launch ----------------
extern "C" void kernel_launch(void* const* d_in, const int* in_sizes, int n_in,
                              void* d_out, int out_size)
{
    const float* Q      = (const float*)d_in[0];
    const float* K      = (const float*)d_in[1];
    const float* V      = (const float*)d_in[2];
    const unsigned char* mask = (const unsigned char*)d_in[3];
    const float* W_q    = (const float*)d_in[4];
    const float* W_k    = (const float*)d_in[5];
    const float* W_v    = (const float*)d_in[6];
    const float* W_o    = (const float*)d_in[7];
    const float* lin1_w = (const float*)d_in[8];
    const float* lin1_b = (const float*)d_in[9];
    const float* lin2_w = (const float*)d_in[10];
    const float* lin2_b = (const float*)d_in[11];
    const float* ln_g   = (const float*)d_in[12];
    const float* ln_b   = (const float*)d_in[13];
    float* out = (float*)d_out;

    float *Qh, *Kh, *Vh, *ctx, *att, *out1, *hid, *ffn;
    cudaGetSymbolAddress((void**)&Qh,  g_Qh);
    cudaGetSymbolAddress((void**)&Kh,  g_Kh);
    cudaGetSymbolAddress((void**)&Vh,  g_Vh);
    cudaGetSymbolAddress((void**)&ctx, g_ctx);
    cudaGetSymbolAddress((void**)&att, g_att);
    cudaGetSymbolAddress((void**)&out1, g_out1);
    cudaGetSymbolAddress((void**)&hid, g_hid);
    cudaGetSymbolAddress((void**)&ffn, g_ffn);

    dim3 ggrid(DD / TBN, MROWS / TBM);   // (4, 128)
    dim3 gblk(256);
    const float invT = 1.0f / (8.0f + 1e-6f);  // 1/(sqrt(DK)+eps), folded into Q proj

    // QKV projections (head-layout epilogue; Q pre-scaled)
    mma_gemm_kernel<EPI_QKV><<<ggrid, gblk>>>(Q, W_q, nullptr, Qh, MROWS, DD, DD, invT);
    mma_gemm_kernel<EPI_QKV><<<ggrid, gblk>>>(K, W_k, nullptr, Kh, MROWS, DD, DD, 1.0f);
    mma_gemm_kernel<EPI_QKV><<<ggrid, gblk>>>(V, W_v, nullptr, Vh, MROWS, DD, DD, 1.0f);

    // attention
    flash_kernel<<<dim3(SS / 128, HH, BB), 256>>>(mask, ctx);

    // output projection + residual LN
    mma_gemm_kernel<EPI_PLAIN><<<ggrid, gblk>>>(ctx, W_o, nullptr, att, MROWS, DD, DD, 1.0f);
    ln_kernel<<<MROWS, DD>>>(att, Q, ln_g, ln_b, out1);

    // FFN
    mma_gemm_kernel<EPI_BIASGELU><<<ggrid, gblk>>>(out1, lin1_w, lin1_b, hid, MROWS, DD, DD, 1.0f);
    mma_gemm_kernel<EPI_BIAS><<<ggrid, gblk>>>(hid, lin2_w, lin2_b, ffn, MROWS, DD, DD, 1.0f);
    ln_kernel<<<MROWS, DD>>>(ffn, out1, ln_g, ln_b, out);
}

// round 5
// speedup vs baseline: 3.9582x; 3.1615x over previous
#include <cuda_runtime.h>
#include <cuda_bf16.h>
#include <cstdint>

// Problem constants
#define BB 16
#define SS 1024
#define DD 512
#define HH 8
#define DKK 64
#define MROWS (BB*SS)          // 16384
#define ELEMS (MROWS*DD)       // 8388608

// ---------------- scratch buffers (no allocation allowed) ----------------
__device__ float g_Qh[ELEMS];   // [B,H,S,DK]
__device__ float g_Kh[ELEMS];
__device__ float g_Vh[ELEMS];
__device__ float g_ctx[ELEMS];  // [B*S, D]
__device__ float g_att[ELEMS];  // ctx @ W_o
__device__ float g_out1[ELEMS]; // after first LN
__device__ float g_hid[ELEMS];  // gelu(out1 @ lin1 + b1)
__device__ float g_ffn[ELEMS];  // hid @ lin2 + b2

// ---------------- helpers ----------------
__device__ __forceinline__ float gelu_tanh_f(float x) {
    float x3 = x * x * x;
    return 0.5f * x * (1.0f + tanhf(0.7978845608028654f * (x + 0.044715f * x3)));
}

__device__ __forceinline__ uint32_t cvt_tf32(float x) {
    uint32_t u;
    asm("cvt.rna.tf32.f32 %0, %1;" : "=r"(u) : "f"(x));
    return u;
}

__device__ __forceinline__ void mma_tf32(
    float& d0, float& d1, float& d2, float& d3,
    uint32_t a0, uint32_t a1, uint32_t a2, uint32_t a3,
    uint32_t b0, uint32_t b1)
{
    asm volatile(
        "mma.sync.aligned.m16n8k8.row.col.f32.tf32.tf32.f32 "
        "{%0,%1,%2,%3}, {%4,%5,%6,%7}, {%8,%9}, {%0,%1,%2,%3};\n"
        : "+f"(d0), "+f"(d1), "+f"(d2), "+f"(d3)
        : "r"(a0), "r"(a1), "r"(a2), "r"(a3), "r"(b0), "r"(b1));
}

__device__ __forceinline__ uint32_t smem_u32(const void* p) {
    return (uint32_t)__cvta_generic_to_shared(p);
}
#define CP_ASYNC16(dst, src) \
    asm volatile("cp.async.cg.shared.global [%0], [%1], 16;\n" :: "r"(dst), "l"(src))
#define CP_COMMIT() asm volatile("cp.async.commit_group;\n")
#define CP_WAIT1()  asm volatile("cp.async.wait_group 1;\n")
#define CP_WAIT0()  asm volatile("cp.async.wait_group 0;\n")

// ================= TF32 GEMM 128x128x32, cp.async double-buffered =========
// 8 warps in 4(m) x 2(n); warp tile 32x64; mma m16n8k8.
// As stored row-major [m][k] pad 36 ; Bs [k][n] pad 136. Both conflict-free
// for fragment reads (36%32=4 -> 4g+tg distinct; 136%32=8 -> 8tg+g distinct).
#define TBM 128
#define TBN 128
#define TBK 32
#define A_STAGE (TBM*36)     // 4608 floats
#define B_STAGE (TBK*136)    // 4352 floats
#define GEMM_SMEM_BYTES (2*(A_STAGE + B_STAGE)*4)   // 71680

enum { EPI_QKV = 0, EPI_PLAIN = 1, EPI_BIAS = 2, EPI_BIASGELU = 3 };

template <int EPI>
__global__ __launch_bounds__(256) void mma_gemm_kernel(
    const float* __restrict__ A,     // [M,K] row-major
    const float* __restrict__ Bw,    // [K,N] row-major
    const float* __restrict__ bias,  // [N] or null
    float* __restrict__ C,
    int M, int N, int K, float scale)
{
    extern __shared__ float gsm[];

    const int tid  = threadIdx.x;
    const int lane = tid & 31;
    const int warp = tid >> 5;      // 0..7
    const int warpM = warp >> 1;    // 0..3
    const int warpN = warp & 1;     // 0..1
    const int g  = lane >> 2;       // 0..7
    const int tg = lane & 3;        // 0..3

    const int mBase = warpM * 32;
    const int nBase = warpN * 64;

    const long rowBlock = (long)blockIdx.y * TBM;
    const int  colBlock = blockIdx.x * TBN;

    float acc[2][8][4];
    #pragma unroll
    for (int i = 0; i < 2; i++)
        #pragma unroll
        for (int j = 0; j < 8; j++)
            #pragma unroll
            for (int c = 0; c < 4; c++) acc[i][j][c] = 0.0f;

    const int nt = K / TBK;   // 16

    // ---- async tile loader ----
    auto load_tile = [&](int kt, int stage) {
        float* AsS = gsm + stage * A_STAGE;
        float* BsS = gsm + 2 * A_STAGE + stage * B_STAGE;
        #pragma unroll
        for (int i = 0; i < 4; i++) {
            int idx = tid + 256 * i;          // 0..1023
            int r = idx >> 3, c = (idx & 7) << 2;
            CP_ASYNC16(smem_u32(&AsS[r * 36 + c]),
                       A + (rowBlock + r) * K + kt + c);
        }
        #pragma unroll
        for (int i = 0; i < 4; i++) {
            int idx = tid + 256 * i;
            int r = idx >> 5, c = (idx & 31) << 2;
            CP_ASYNC16(smem_u32(&BsS[r * 136 + c]),
                       Bw + (long)(kt + r) * N + colBlock + c);
        }
    };

    load_tile(0, 0);
    CP_COMMIT();

    int buf = 0;
    for (int it = 0; it < nt; it++) {
        if (it + 1 < nt) {
            load_tile((it + 1) * TBK, buf ^ 1);
            CP_COMMIT();
            CP_WAIT1();
        } else {
            CP_WAIT0();
        }
        __syncthreads();

        const float* AsS = gsm + buf * A_STAGE;
        const float* BsS = gsm + 2 * A_STAGE + buf * B_STAGE;

        #pragma unroll
        for (int kk = 0; kk < 4; kk++) {
            const int k0 = kk * 8;
            uint32_t af[2][4];
            #pragma unroll
            for (int mi = 0; mi < 2; mi++) {
                int m = mBase + mi * 16 + g;
                af[mi][0] = __float_as_uint(AsS[m * 36 + k0 + tg]);
                af[mi][1] = __float_as_uint(AsS[(m + 8) * 36 + k0 + tg]);
                af[mi][2] = __float_as_uint(AsS[m * 36 + k0 + tg + 4]);
                af[mi][3] = __float_as_uint(AsS[(m + 8) * 36 + k0 + tg + 4]);
            }
            uint32_t bf[8][2];
            #pragma unroll
            for (int ni = 0; ni < 8; ni++) {
                int n = nBase + ni * 8 + g;
                bf[ni][0] = __float_as_uint(BsS[(k0 + tg) * 136 + n]);
                bf[ni][1] = __float_as_uint(BsS[(k0 + tg + 4) * 136 + n]);
            }
            #pragma unroll
            for (int mi = 0; mi < 2; mi++)
                #pragma unroll
                for (int ni = 0; ni < 8; ni++)
                    mma_tf32(acc[mi][ni][0], acc[mi][ni][1], acc[mi][ni][2], acc[mi][ni][3],
                             af[mi][0], af[mi][1], af[mi][2], af[mi][3],
                             bf[ni][0], bf[ni][1]);
        }
        __syncthreads();
        buf ^= 1;
    }

    // ---- epilogue ----
    #pragma unroll
    for (int mi = 0; mi < 2; mi++) {
        #pragma unroll
        for (int ri = 0; ri < 2; ri++) {
            int m = (int)rowBlock + mBase + mi * 16 + g + ri * 8;
            #pragma unroll
            for (int ni = 0; ni < 8; ni++) {
                int n = colBlock + nBase + ni * 8 + tg * 2;
                float v0 = acc[mi][ni][ri * 2 + 0];
                float v1 = acc[mi][ni][ri * 2 + 1];
                if (EPI == EPI_QKV) {
                    int b = m >> 10, s = m & 1023;
                    int h = n >> 6, dk = n & 63;
                    float2 o; o.x = v0 * scale; o.y = v1 * scale;
                    *(float2*)&C[(((((long)b * HH + h) << 10) + s) << 6) + dk] = o;
                } else if (EPI == EPI_PLAIN) {
                    float2 o; o.x = v0; o.y = v1;
                    *(float2*)&C[(long)m * N + n] = o;
                } else if (EPI == EPI_BIAS) {
                    float2 o; o.x = v0 + bias[n]; o.y = v1 + bias[n + 1];
                    *(float2*)&C[(long)m * N + n] = o;
                } else {
                    float2 o;
                    o.x = gelu_tanh_f(v0 + bias[n]);
                    o.y = gelu_tanh_f(v1 + bias[n + 1]);
                    *(float2*)&C[(long)m * N + n] = o;
                }
            }
        }
    }
}

// ================= Tensor-core flash attention ============================
// Br=64 (4 warps x m16), Bc=64, DK=64, tf32 mma for QK^T and P.V.
// smem (floats): Ks[64][68] @0 (4352) | Vs[64][72] @4352 (4608) |
//                Ps 4x[16][68] @8960 (4352) | mask 64B @13312
#define FL_KS 0
#define FL_VS 4352
#define FL_PS 8960
#define FL_MS 13312
#define FLASH_SMEM_BYTES ((13312 + 16) * 4)   // 53312

__global__ __launch_bounds__(128) void flash_tc_kernel(
    const unsigned char* __restrict__ mask, float* __restrict__ ctx)
{
    extern __shared__ float fsm[];
    float* Ks = fsm + FL_KS;
    float* Vs = fsm + FL_VS;
    unsigned char* Msk = (unsigned char*)(fsm + FL_MS);

    const int t = threadIdx.x;
    const int lane = t & 31, warp = t >> 5;
    const int g = lane >> 2, tg = lane & 3;
    const int qt = blockIdx.x;      // 0..15
    const int h = blockIdx.y;
    const int b = blockIdx.z;
    const long base = ((long)(b * HH + h)) << 16;   // *S*DK
    const int q0 = qt * 64;
    const int rowg = warp * 16 + g;                 // local row (c0/c1)
    const int qg0 = q0 + rowg;                      // global query rows
    const int qg1 = qg0 + 8;
    float* Pw = fsm + FL_PS + warp * (16 * 68);

    // ---- stage Q tile through Ks, build A-fragments (rna-converted) ----
    #pragma unroll
    for (int i = 0; i < 8; i++) {
        int idx = t + 128 * i;                 // 0..1023
        int r = idx >> 4, c = (idx & 15) << 2;
        *(float4*)&Ks[r * 68 + c] = *(const float4*)&g_Qh[base + (long)(q0 + r) * 64 + c];
    }
    __syncthreads();
    uint32_t qf[8][4];
    #pragma unroll
    for (int kk = 0; kk < 8; kk++) {
        int k0 = kk * 8;
        qf[kk][0] = cvt_tf32(Ks[rowg * 68 + k0 + tg]);
        qf[kk][1] = cvt_tf32(Ks[(rowg + 8) * 68 + k0 + tg]);
        qf[kk][2] = cvt_tf32(Ks[rowg * 68 + k0 + tg + 4]);
        qf[kk][3] = cvt_tf32(Ks[(rowg + 8) * 68 + k0 + tg + 4]);
    }
    __syncthreads();

    float o[8][4];
    #pragma unroll
    for (int i = 0; i < 8; i++)
        #pragma unroll
        for (int j = 0; j < 4; j++) o[i][j] = 0.0f;
    float m0 = -1e30f, m1 = -1e30f, l0 = 0.0f, l1 = 0.0f;

    const int ntiles = qt + 1;
    for (int kt = 0; kt < ntiles; kt++) {
        const int kb = kt * 64;

        // ---- load K,V tiles (+pad mask) ----
        #pragma unroll
        for (int i = 0; i < 8; i++) {
            int idx = t + 128 * i;
            int r = idx >> 4, c = (idx & 15) << 2;
            *(float4*)&Ks[r * 68 + c] = *(const float4*)&g_Kh[base + (long)(kb + r) * 64 + c];
            *(float4*)&Vs[r * 72 + c] = *(const float4*)&g_Vh[base + (long)(kb + r) * 64 + c];
        }
        if (t < 64) Msk[t] = mask[b * SS + kb + t];
        __syncthreads();

        // ---- S = Q . K^T (per warp: m16 x n64 x k64) ----
        float s[8][4];
        #pragma unroll
        for (int i = 0; i < 8; i++)
            #pragma unroll
            for (int j = 0; j < 4; j++) s[i][j] = 0.0f;
        #pragma unroll
        for (int kk = 0; kk < 8; kk++) {
            int k0 = kk * 8;
            #pragma unroll
            for (int ni = 0; ni < 8; ni++) {
                uint32_t b0 = __float_as_uint(Ks[(ni * 8 + g) * 68 + k0 + tg]);
                uint32_t b1 = __float_as_uint(Ks[(ni * 8 + g) * 68 + k0 + tg + 4]);
                mma_tf32(s[ni][0], s[ni][1], s[ni][2], s[ni][3],
                         qf[kk][0], qf[kk][1], qf[kk][2], qf[kk][3], b0, b1);
            }
        }

        // ---- mask + row max (rows qg0, qg1; cols kb + ni*8 + 2tg{,+1}) ----
        float tmax0 = -1e30f, tmax1 = -1e30f;
        #pragma unroll
        for (int ni = 0; ni < 8; ni++) {
            int cl = ni * 8 + 2 * tg;
            int c0g = kb + cl, c1g = c0g + 1;
            bool pm0 = Msk[cl] != 0, pm1 = Msk[cl + 1] != 0;
            if (c0g > qg0 || pm0) s[ni][0] = -1e30f;
            if (c1g > qg0 || pm1) s[ni][1] = -1e30f;
            if (c0g > qg1 || pm0) s[ni][2] = -1e30f;
            if (c1g > qg1 || pm1) s[ni][3] = -1e30f;
            tmax0 = fmaxf(tmax0, fmaxf(s[ni][0], s[ni][1]));
            tmax1 = fmaxf(tmax1, fmaxf(s[ni][2], s[ni][3]));
        }
        #pragma unroll
        for (int off = 1; off <= 2; off <<= 1) {
            tmax0 = fmaxf(tmax0, __shfl_xor_sync(0xffffffffu, tmax0, off));
            tmax1 = fmaxf(tmax1, __shfl_xor_sync(0xffffffffu, tmax1, off));
        }

        float mnew0 = fmaxf(m0, tmax0), mnew1 = fmaxf(m1, tmax1);
        float corr0 = __expf(m0 - mnew0), corr1 = __expf(m1 - mnew1);

        // ---- P = exp(S - m), write to warp-private smem; partial row sums ----
        float ls0 = 0.0f, ls1 = 0.0f;
        #pragma unroll
        for (int ni = 0; ni < 8; ni++) {
            float p00 = __expf(s[ni][0] - mnew0);
            float p01 = __expf(s[ni][1] - mnew0);
            float p10 = __expf(s[ni][2] - mnew1);
            float p11 = __expf(s[ni][3] - mnew1);
            ls0 += p00 + p01;
            ls1 += p10 + p11;
            int cl = ni * 8 + 2 * tg;
            *(float2*)&Pw[g * 68 + cl] = make_float2(p00, p01);
            *(float2*)&Pw[(g + 8) * 68 + cl] = make_float2(p10, p11);
        }
        #pragma unroll
        for (int off = 1; off <= 2; off <<= 1) {
            ls0 += __shfl_xor_sync(0xffffffffu, ls0, off);
            ls1 += __shfl_xor_sync(0xffffffffu, ls1, off);
        }
        l0 = l0 * corr0 + ls0;
        l1 = l1 * corr1 + ls1;
        m0 = mnew0; m1 = mnew1;

        // rescale O
        #pragma unroll
        for (int ni = 0; ni < 8; ni++) {
            o[ni][0] *= corr0; o[ni][1] *= corr0;
            o[ni][2] *= corr1; o[ni][3] *= corr1;
        }
        __syncwarp();

        // ---- O += P . V (m16 x n64(dk) x k64(key)) ----
        #pragma unroll
        for (int kk = 0; kk < 8; kk++) {
            int k0 = kk * 8;
            uint32_t a0 = __float_as_uint(Pw[g * 68 + k0 + tg]);
            uint32_t a1 = __float_as_uint(Pw[(g + 8) * 68 + k0 + tg]);
            uint32_t a2 = __float_as_uint(Pw[g * 68 + k0 + tg + 4]);
            uint32_t a3 = __float_as_uint(Pw[(g + 8) * 68 + k0 + tg + 4]);
            #pragma unroll
            for (int ni = 0; ni < 8; ni++) {
                uint32_t b0 = __float_as_uint(Vs[(k0 + tg) * 72 + ni * 8 + g]);
                uint32_t b1 = __float_as_uint(Vs[(k0 + tg + 4) * 72 + ni * 8 + g]);
                mma_tf32(o[ni][0], o[ni][1], o[ni][2], o[ni][3], a0, a1, a2, a3, b0, b1);
            }
        }
        __syncthreads();   // all warps done with Ks/Vs before next tile load
    }

    // ---- epilogue: normalize + store to ctx [b*S+q][h*64+dk] ----
    const float inv0 = 1.0f / l0, inv1 = 1.0f / l1;
    float* dst0 = &ctx[((long)(b * SS + qg0)) * DD + h * DKK];
    float* dst1 = &ctx[((long)(b * SS + qg1)) * DD + h * DKK];
    #pragma unroll
    for (int ni = 0; ni < 8; ni++) {
        int cl = ni * 8 + 2 * tg;
        *(float2*)&dst0[cl] = make_float2(o[ni][0] * inv0, o[ni][1] * inv0);
        *(float2*)&dst1[cl] = make_float2(o[ni][2] * inv1, o[ni][3] * inv1);
    }
}

// ---------------- residual + LayerNorm (row of 512, 512 threads) ----------------
__global__ __launch_bounds__(512) void ln_kernel(
    const float* __restrict__ X, const float* __restrict__ R,
    const float* __restrict__ g, const float* __restrict__ bta,
    float* __restrict__ out)
{
    const int row = blockIdx.x;
    const int t = threadIdx.x;
    const long off = (long)row * DD + t;
    const float xv = X[off] + R[off];

    __shared__ float red[16];
    __shared__ float sh_mu, sh_rstd;

    float s = xv;
    #pragma unroll
    for (int o = 16; o; o >>= 1) s += __shfl_xor_sync(0xffffffffu, s, o);
    if ((t & 31) == 0) red[t >> 5] = s;
    __syncthreads();
    if (t < 16) {
        float v = red[t];
        #pragma unroll
        for (int o = 8; o; o >>= 1) v += __shfl_xor_sync(0x0000ffffu, v, o);
        if (t == 0) sh_mu = v * (1.0f / DD);
    }
    __syncthreads();
    const float mu = sh_mu;
    const float d = xv - mu;

    s = d * d;
    #pragma unroll
    for (int o = 16; o; o >>= 1) s += __shfl_xor_sync(0xffffffffu, s, o);
    __syncthreads();
    if ((t & 31) == 0) red[t >> 5] = s;
    __syncthreads();
    if (t < 16) {
        float v = red[t];
        #pragma unroll
        for (int o = 8; o; o >>= 1) v += __shfl_xor_sync(0x0000ffffu, v, o);
        if (t == 0) sh_rstd = rsqrtf(v * (1.0f / DD) + 1e-5f);
    }
    __syncthreads();

    out[off] = d * sh_rstd * g[t] + bta[t];
}

// ---------------- launch ----------------
extern "C" void kernel_launch(void* const* d_in, const int* in_sizes, int n_in,
                              void* d_out, int out_size)
{
    const float* Q      = (const float*)d_in[0];
    const float* K      = (const float*)d_in[1];
    const float* V      = (const float*)d_in[2];
    const unsigned char* mask = (const unsigned char*)d_in[3];
    const float* W_q    = (const float*)d_in[4];
    const float* W_k    = (const float*)d_in[5];
    const float* W_v    = (const float*)d_in[6];
    const float* W_o    = (const float*)d_in[7];
    const float* lin1_w = (const float*)d_in[8];
    const float* lin1_b = (const float*)d_in[9];
    const float* lin2_w = (const float*)d_in[10];
    const float* lin2_b = (const float*)d_in[11];
    const float* ln_g   = (const float*)d_in[12];
    const float* ln_b   = (const float*)d_in[13];
    float* out = (float*)d_out;

    float *Qh, *Kh, *Vh, *ctx, *att, *out1, *hid, *ffn;
    cudaGetSymbolAddress((void**)&Qh,  g_Qh);
    cudaGetSymbolAddress((void**)&Kh,  g_Kh);
    cudaGetSymbolAddress((void**)&Vh,  g_Vh);
    cudaGetSymbolAddress((void**)&ctx, g_ctx);
    cudaGetSymbolAddress((void**)&att, g_att);
    cudaGetSymbolAddress((void**)&out1, g_out1);
    cudaGetSymbolAddress((void**)&hid, g_hid);
    cudaGetSymbolAddress((void**)&ffn, g_ffn);

    // dynamic smem opt-in (host-side attribute set; capture-safe)
    cudaFuncSetAttribute(mma_gemm_kernel<EPI_QKV>,
                         cudaFuncAttributeMaxDynamicSharedMemorySize, GEMM_SMEM_BYTES);
    cudaFuncSetAttribute(mma_gemm_kernel<EPI_PLAIN>,
                         cudaFuncAttributeMaxDynamicSharedMemorySize, GEMM_SMEM_BYTES);
    cudaFuncSetAttribute(mma_gemm_kernel<EPI_BIAS>,
                         cudaFuncAttributeMaxDynamicSharedMemorySize, GEMM_SMEM_BYTES);
    cudaFuncSetAttribute(mma_gemm_kernel<EPI_BIASGELU>,
                         cudaFuncAttributeMaxDynamicSharedMemorySize, GEMM_SMEM_BYTES);
    cudaFuncSetAttribute(flash_tc_kernel,
                         cudaFuncAttributeMaxDynamicSharedMemorySize, FLASH_SMEM_BYTES);

    dim3 ggrid(DD / TBN, MROWS / TBM);   // (4, 128)
    dim3 gblk(256);
    const float invT = 1.0f / (8.0f + 1e-6f);  // 1/(sqrt(DK)+eps), folded into Q proj

    // QKV projections (head-layout epilogue; Q pre-scaled)
    mma_gemm_kernel<EPI_QKV><<<ggrid, gblk, GEMM_SMEM_BYTES>>>(Q, W_q, nullptr, Qh, MROWS, DD, DD, invT);
    mma_gemm_kernel<EPI_QKV><<<ggrid, gblk, GEMM_SMEM_BYTES>>>(K, W_k, nullptr, Kh, MROWS, DD, DD, 1.0f);
    mma_gemm_kernel<EPI_QKV><<<ggrid, gblk, GEMM_SMEM_BYTES>>>(V, W_v, nullptr, Vh, MROWS, DD, DD, 1.0f);

    // attention (tensor-core flash)
    flash_tc_kernel<<<dim3(SS / 64, HH, BB), 128, FLASH_SMEM_BYTES>>>(mask, ctx);

    // output projection + residual LN
    mma_gemm_kernel<EPI_PLAIN><<<ggrid, gblk, GEMM_SMEM_BYTES>>>(ctx, W_o, nullptr, att, MROWS, DD, DD, 1.0f);
    ln_kernel<<<MROWS, DD>>>(att, Q, ln_g, ln_b, out1);

    // FFN
    mma_gemm_kernel<EPI_BIASGELU><<<ggrid, gblk, GEMM_SMEM_BYTES>>>(out1, lin1_w, lin1_b, hid, MROWS, DD, DD, 1.0f);
    mma_gemm_kernel<EPI_BIAS><<<ggrid, gblk, GEMM_SMEM_BYTES>>>(hid, lin2_w, lin2_b, ffn, MROWS, DD, DD, 1.0f);
    ln_kernel<<<MROWS, DD>>>(ffn, out1, ln_g, ln_b, out);
}

// round 11
// speedup vs baseline: 4.4059x; 1.1131x over previous
#include <cuda_runtime.h>
#include <cuda_bf16.h>
#include <cstdint>

// Problem constants
#define BB 16
#define SS 1024
#define DD 512
#define HH 8
#define DKK 64
#define MROWS (BB*SS)          // 16384
#define ELEMS (MROWS*DD)       // 8388608
#define WSZ (DD*DD)            // 262144

// ---------------- scratch buffers (no allocation allowed) ----------------
__device__ float g_Qh[ELEMS];   // [B,H,S,DK]  (tf32-rounded)
__device__ float g_Kh[ELEMS];
__device__ float g_Vh[ELEMS];
__device__ float g_ctx[ELEMS];  // [B*S, D]
__device__ float g_att[ELEMS];  // ctx @ W_o
__device__ float g_out1[ELEMS]; // after first LN
__device__ float g_hid[ELEMS];  // gelu(out1 @ lin1 + b1) (tf32-rounded)
__device__ float g_ffn[ELEMS];  // hid @ lin2 + b2
__device__ float g_Wr[6 * WSZ]; // tf32-rounded weights, original [k][n] layout

// ---------------- helpers ----------------
__device__ __forceinline__ float gelu_tanh_f(float x) {
    float x3 = x * x * x;
    return 0.5f * x * (1.0f + tanhf(0.7978845608028654f * (x + 0.044715f * x3)));
}

__device__ __forceinline__ uint32_t cvt_tf32(float x) {
    uint32_t u;
    asm("cvt.rna.tf32.f32 %0, %1;" : "=r"(u) : "f"(x));
    return u;
}
__device__ __forceinline__ float rna_tf32f(float x) {
    return __uint_as_float(cvt_tf32(x));
}

__device__ __forceinline__ void mma_tf32(
    float& d0, float& d1, float& d2, float& d3,
    uint32_t a0, uint32_t a1, uint32_t a2, uint32_t a3,
    uint32_t b0, uint32_t b1)
{
    asm volatile(
        "mma.sync.aligned.m16n8k8.row.col.f32.tf32.tf32.f32 "
        "{%0,%1,%2,%3}, {%4,%5,%6,%7}, {%8,%9}, {%0,%1,%2,%3};\n"
        : "+f"(d0), "+f"(d1), "+f"(d2), "+f"(d3)
        : "r"(a0), "r"(a1), "r"(a2), "r"(a3), "r"(b0), "r"(b1));
}

__device__ __forceinline__ uint32_t smem_u32(const void* p) {
    return (uint32_t)__cvta_generic_to_shared(p);
}
#define CP_ASYNC16(dst, src) \
    asm volatile("cp.async.cg.shared.global [%0], [%1], 16;\n" :: "r"(dst), "l"(src))
#define CP_COMMIT() asm volatile("cp.async.commit_group;\n")
#define CP_WAIT0()  asm volatile("cp.async.wait_group 0;\n")

// ============ weight rna pre-round (layout preserved [k][n]) ==============
__global__ __launch_bounds__(256) void wround_kernel(
    const float* __restrict__ W0, const float* __restrict__ W1,
    const float* __restrict__ W2, const float* __restrict__ W3,
    const float* __restrict__ W4, const float* __restrict__ W5,
    float* __restrict__ out)
{
    const float* Ws[6] = {W0, W1, W2, W3, W4, W5};
    const int z = blockIdx.y;
    const int idx = blockIdx.x * 256 + threadIdx.x;   // float4 index, 65536/matrix
    float4 v = ((const float4*)Ws[z])[idx];
    v.x = rna_tf32f(v.x); v.y = rna_tf32f(v.y);
    v.z = rna_tf32f(v.z); v.w = rna_tf32f(v.w);
    ((float4*)(out + (long)z * WSZ))[idx] = v;
}

// ================= TF32 GEMM 128x128x32, cp.async B + reg-staged A ========
// 8 warps in 4(m) x 2(n); warp tile 32x64; mma m16n8k8.
// As row-major [m][k] pad 36 (rna at STS); Bs [k][n] pad 136 (pre-rounded
// weights via cp.async).
//
// Pipeline ordering (one barrier per iter, race-free):
//   barrier at END of each iteration; prefetch of tile it+1 (cp.async B and
//   LDG A) issued at TOP of iteration it — i.e. strictly AFTER the barrier
//   that closed iteration it-1, which fenced all reads of buffer buf^1.
//   CP_WAIT0 + end barrier publish tile it+1 before iteration it+1 reads it.
#define TBK 32
#define A_STAGE (128*36)     // 4608 floats
#define B_STAGE (TBK*136)    // 4352 floats
#define GEMM_SMEM_BYTES (2*(A_STAGE + B_STAGE)*4)   // 71680

enum { EPI_QKV = 0, EPI_PLAIN = 1, EPI_BIAS = 2, EPI_BIASGELU = 3 };

template <int EPI>
__device__ __forceinline__ void gemm_body(
    const float* __restrict__ A,     // [16384, 512] fp32 (any rounding)
    const float* __restrict__ Bw,    // [512, 512] fp32, pre-rounded tf32
    const float* __restrict__ bias,  // [512] or null
    float* __restrict__ C, float scale)
{
    extern __shared__ float gsm[];

    const int tid  = threadIdx.x;
    const int lane = tid & 31;
    const int warp = tid >> 5;
    const int warpM = warp >> 1;    // 0..3
    const int warpN = warp & 1;     // 0..1
    const int g  = lane >> 2;       // 0..7
    const int tg = lane & 3;        // 0..3

    const int mBase = warpM * 32;
    const int nBase = warpN * 64;

    const long rowBlock = (long)blockIdx.y * 128;
    const int  colBlock = blockIdx.x * 128;

    // loader mapping (1024 float4 per tile, 4 per thread)
    const int lrA = tid >> 3;             // 0..31 -> rows lrA, +32, +64, +96
    const int lcA = (tid & 7) << 2;       // 0..28
    const int lrB = tid >> 5;             // 0..7  -> k-rows lrB, +8, +16, +24
    const int lcB = (tid & 31) << 2;      // 0..124

    float acc[2][8][4];
    #pragma unroll
    for (int i = 0; i < 2; i++)
        #pragma unroll
        for (int j = 0; j < 8; j++)
            #pragma unroll
            for (int c = 0; c < 4; c++) acc[i][j][c] = 0.0f;

    const int nt = 512 / TBK;   // 16

    auto issueB = [&](int kt, int stage) {
        float* BsS = gsm + 2 * A_STAGE + stage * B_STAGE;
        #pragma unroll
        for (int i = 0; i < 4; i++) {
            int r = lrB + 8 * i;
            CP_ASYNC16(smem_u32(&BsS[r * 136 + lcB]),
                       Bw + (long)(kt + r) * 512 + colBlock + lcB);
        }
    };
    auto ldA = [&](int kt, float4* ar) {
        #pragma unroll
        for (int i = 0; i < 4; i++) {
            int r = lrA + 32 * i;
            ar[i] = *(const float4*)(A + (rowBlock + r) * 512 + kt + lcA);
        }
    };
    auto stA = [&](int stage, const float4* ar) {
        float* AsS = gsm + stage * A_STAGE;
        #pragma unroll
        for (int i = 0; i < 4; i++) {
            int r = lrA + 32 * i;
            float4 v = ar[i];
            v.x = rna_tf32f(v.x); v.y = rna_tf32f(v.y);
            v.z = rna_tf32f(v.z); v.w = rna_tf32f(v.w);
            *(float4*)&AsS[r * 36 + lcA] = v;
        }
    };

    // ---- prologue: tile 0 into buffer 0, published to all warps ----
    {
        float4 ar[4];
        issueB(0, 0);
        CP_COMMIT();
        ldA(0, ar);
        stA(0, ar);
        CP_WAIT0();
        __syncthreads();
    }

    int buf = 0;
    for (int it = 0; it < nt; it++) {
        float4 ar[4];
        const bool pre = (it + 1 < nt);
        if (pre) {
            // Safe: all reads of buffer buf^1 finished before the barrier
            // that ended iteration it-1 (or prologue).
            issueB((it + 1) * TBK, buf ^ 1);
            CP_COMMIT();
            ldA((it + 1) * TBK, ar);   // LDG overlaps MMA below
        }

        const float* AsS = gsm + buf * A_STAGE;
        const float* BsS = gsm + 2 * A_STAGE + buf * B_STAGE;

        #pragma unroll
        for (int kk = 0; kk < 4; kk++) {
            const int k0 = kk * 8;
            uint32_t af[2][4];
            #pragma unroll
            for (int mi = 0; mi < 2; mi++) {
                int m = mBase + mi * 16 + g;
                af[mi][0] = __float_as_uint(AsS[m * 36 + k0 + tg]);
                af[mi][1] = __float_as_uint(AsS[(m + 8) * 36 + k0 + tg]);
                af[mi][2] = __float_as_uint(AsS[m * 36 + k0 + tg + 4]);
                af[mi][3] = __float_as_uint(AsS[(m + 8) * 36 + k0 + tg + 4]);
            }
            uint32_t bf[8][2];
            #pragma unroll
            for (int ni = 0; ni < 8; ni++) {
                int n = nBase + ni * 8 + g;
                bf[ni][0] = __float_as_uint(BsS[(k0 + tg) * 136 + n]);
                bf[ni][1] = __float_as_uint(BsS[(k0 + tg + 4) * 136 + n]);
            }
            #pragma unroll
            for (int mi = 0; mi < 2; mi++)
                #pragma unroll
                for (int ni = 0; ni < 8; ni++)
                    mma_tf32(acc[mi][ni][0], acc[mi][ni][1], acc[mi][ni][2], acc[mi][ni][3],
                             af[mi][0], af[mi][1], af[mi][2], af[mi][3],
                             bf[ni][0], bf[ni][1]);
        }

        if (pre) {
            stA(buf ^ 1, ar);   // writes buf^1: readers fenced by prior barrier
            CP_WAIT0();         // B(it+1) landed in smem
        }
        __syncthreads();        // close iteration: publish tile it+1, fence reads of buf
        buf ^= 1;
    }

    // ---- epilogue ----
    #pragma unroll
    for (int mi = 0; mi < 2; mi++) {
        #pragma unroll
        for (int ri = 0; ri < 2; ri++) {
            int m = (int)rowBlock + mBase + mi * 16 + g + ri * 8;
            #pragma unroll
            for (int ni = 0; ni < 8; ni++) {
                int n = colBlock + nBase + ni * 8 + tg * 2;
                float v0 = acc[mi][ni][ri * 2 + 0];
                float v1 = acc[mi][ni][ri * 2 + 1];
                if (EPI == EPI_QKV) {
                    // store rna-rounded so flash operands are exact tf32
                    int b = m >> 10, s = m & 1023;
                    int h = n >> 6, dk = n & 63;
                    float2 o;
                    o.x = rna_tf32f(v0 * scale);
                    o.y = rna_tf32f(v1 * scale);
                    *(float2*)&C[(((((long)b * HH + h) << 10) + s) << 6) + dk] = o;
                } else if (EPI == EPI_PLAIN) {
                    float2 o; o.x = v0; o.y = v1;
                    *(float2*)&C[(long)m * DD + n] = o;
                } else if (EPI == EPI_BIAS) {
                    float2 o; o.x = v0 + bias[n]; o.y = v1 + bias[n + 1];
                    *(float2*)&C[(long)m * DD + n] = o;
                } else {  // EPI_BIASGELU -> hid (rounded: consumed only by lin2)
                    float2 o;
                    o.x = rna_tf32f(gelu_tanh_f(v0 + bias[n]));
                    o.y = rna_tf32f(gelu_tanh_f(v1 + bias[n + 1]));
                    *(float2*)&C[(long)m * DD + n] = o;
                }
            }
        }
    }
}

template <int EPI>
__global__ __launch_bounds__(256, 2) void gemm_kernel(
    const float* __restrict__ A, const float* __restrict__ Bw,
    const float* __restrict__ bias, float* __restrict__ C, float scale)
{
    gemm_body<EPI>(A, Bw, bias, C, scale);
}

// fused QKV: blockIdx.z selects (input, weight, output, scale)
__global__ __launch_bounds__(256, 2) void gemm_qkv_kernel(
    const float* __restrict__ Q, const float* __restrict__ K,
    const float* __restrict__ V, const float* __restrict__ Wr,
    float invT)
{
    const int z = blockIdx.z;
    const float* A = (z == 0) ? Q : (z == 1) ? K : V;
    float* C = (z == 0) ? g_Qh : (z == 1) ? g_Kh : g_Vh;
    gemm_body<EPI_QKV>(A, Wr + (long)z * WSZ, nullptr, C,
                       (z == 0) ? invT : 1.0f);
}

// ================= Tensor-core flash attention (operands pre-rounded) =====
#define FL_KS 0
#define FL_VS 4352
#define FL_PS 8960
#define FL_MS 13312
#define FLASH_SMEM_BYTES ((13312 + 16) * 4)

__global__ __launch_bounds__(128) void flash_tc_kernel(
    const unsigned char* __restrict__ mask, float* __restrict__ ctx)
{
    extern __shared__ float fsm[];
    float* Ks = fsm + FL_KS;
    float* Vs = fsm + FL_VS;
    unsigned char* Msk = (unsigned char*)(fsm + FL_MS);

    const int t = threadIdx.x;
    const int lane = t & 31, warp = t >> 5;
    const int g = lane >> 2, tg = lane & 3;
    const int qt = blockIdx.x;
    const int h = blockIdx.y;
    const int b = blockIdx.z;
    const long base = ((long)(b * HH + h)) << 16;
    const int q0 = qt * 64;
    const int rowg = warp * 16 + g;
    const int qg0 = q0 + rowg;
    const int qg1 = qg0 + 8;
    float* Pw = fsm + FL_PS + warp * (16 * 68);

    // Q fragments (values already tf32-exact from QKV epilogue)
    #pragma unroll
    for (int i = 0; i < 8; i++) {
        int idx = t + 128 * i;
        int r = idx >> 4, c = (idx & 15) << 2;
        *(float4*)&Ks[r * 68 + c] = *(const float4*)&g_Qh[base + (long)(q0 + r) * 64 + c];
    }
    __syncthreads();
    uint32_t qf[8][4];
    #pragma unroll
    for (int kk = 0; kk < 8; kk++) {
        int k0 = kk * 8;
        qf[kk][0] = __float_as_uint(Ks[rowg * 68 + k0 + tg]);
        qf[kk][1] = __float_as_uint(Ks[(rowg + 8) * 68 + k0 + tg]);
        qf[kk][2] = __float_as_uint(Ks[rowg * 68 + k0 + tg + 4]);
        qf[kk][3] = __float_as_uint(Ks[(rowg + 8) * 68 + k0 + tg + 4]);
    }
    __syncthreads();

    float o[8][4];
    #pragma unroll
    for (int i = 0; i < 8; i++)
        #pragma unroll
        for (int j = 0; j < 4; j++) o[i][j] = 0.0f;
    float m0 = -1e30f, m1 = -1e30f, l0 = 0.0f, l1 = 0.0f;

    const int ntiles = qt + 1;
    for (int kt = 0; kt < ntiles; kt++) {
        const int kb = kt * 64;

        #pragma unroll
        for (int i = 0; i < 8; i++) {
            int idx = t + 128 * i;
            int r = idx >> 4, c = (idx & 15) << 2;
            *(float4*)&Ks[r * 68 + c] = *(const float4*)&g_Kh[base + (long)(kb + r) * 64 + c];
            *(float4*)&Vs[r * 72 + c] = *(const float4*)&g_Vh[base + (long)(kb + r) * 64 + c];
        }
        if (t < 64) Msk[t] = mask[b * SS + kb + t];
        __syncthreads();

        float s[8][4];
        #pragma unroll
        for (int i = 0; i < 8; i++)
            #pragma unroll
            for (int j = 0; j < 4; j++) s[i][j] = 0.0f;
        #pragma unroll
        for (int kk = 0; kk < 8; kk++) {
            int k0 = kk * 8;
            #pragma unroll
            for (int ni = 0; ni < 8; ni++) {
                uint32_t b0 = __float_as_uint(Ks[(ni * 8 + g) * 68 + k0 + tg]);
                uint32_t b1 = __float_as_uint(Ks[(ni * 8 + g) * 68 + k0 + tg + 4]);
                mma_tf32(s[ni][0], s[ni][1], s[ni][2], s[ni][3],
                         qf[kk][0], qf[kk][1], qf[kk][2], qf[kk][3], b0, b1);
            }
        }

        float tmax0 = -1e30f, tmax1 = -1e30f;
        #pragma unroll
        for (int ni = 0; ni < 8; ni++) {
            int cl = ni * 8 + 2 * tg;
            int c0g = kb + cl, c1g = c0g + 1;
            bool pm0 = Msk[cl] != 0, pm1 = Msk[cl + 1] != 0;
            if (c0g > qg0 || pm0) s[ni][0] = -1e30f;
            if (c1g > qg0 || pm1) s[ni][1] = -1e30f;
            if (c0g > qg1 || pm0) s[ni][2] = -1e30f;
            if (c1g > qg1 || pm1) s[ni][3] = -1e30f;
            tmax0 = fmaxf(tmax0, fmaxf(s[ni][0], s[ni][1]));
            tmax1 = fmaxf(tmax1, fmaxf(s[ni][2], s[ni][3]));
        }
        #pragma unroll
        for (int off = 1; off <= 2; off <<= 1) {
            tmax0 = fmaxf(tmax0, __shfl_xor_sync(0xffffffffu, tmax0, off));
            tmax1 = fmaxf(tmax1, __shfl_xor_sync(0xffffffffu, tmax1, off));
        }

        float mnew0 = fmaxf(m0, tmax0), mnew1 = fmaxf(m1, tmax1);
        float corr0 = __expf(m0 - mnew0), corr1 = __expf(m1 - mnew1);

        // P = rna(exp(S-m)) stored (rounded values used for BOTH l and P.V)
        float ls0 = 0.0f, ls1 = 0.0f;
        #pragma unroll
        for (int ni = 0; ni < 8; ni++) {
            float p00 = rna_tf32f(__expf(s[ni][0] - mnew0));
            float p01 = rna_tf32f(__expf(s[ni][1] - mnew0));
            float p10 = rna_tf32f(__expf(s[ni][2] - mnew1));
            float p11 = rna_tf32f(__expf(s[ni][3] - mnew1));
            ls0 += p00 + p01;
            ls1 += p10 + p11;
            int cl = ni * 8 + 2 * tg;
            *(float2*)&Pw[g * 68 + cl] = make_float2(p00, p01);
            *(float2*)&Pw[(g + 8) * 68 + cl] = make_float2(p10, p11);
        }
        #pragma unroll
        for (int off = 1; off <= 2; off <<= 1) {
            ls0 += __shfl_xor_sync(0xffffffffu, ls0, off);
            ls1 += __shfl_xor_sync(0xffffffffu, ls1, off);
        }
        l0 = l0 * corr0 + ls0;
        l1 = l1 * corr1 + ls1;
        m0 = mnew0; m1 = mnew1;

        #pragma unroll
        for (int ni = 0; ni < 8; ni++) {
            o[ni][0] *= corr0; o[ni][1] *= corr0;
            o[ni][2] *= corr1; o[ni][3] *= corr1;
        }
        __syncwarp();

        #pragma unroll
        for (int kk = 0; kk < 8; kk++) {
            int k0 = kk * 8;
            uint32_t a0 = __float_as_uint(Pw[g * 68 + k0 + tg]);
            uint32_t a1 = __float_as_uint(Pw[(g + 8) * 68 + k0 + tg]);
            uint32_t a2 = __float_as_uint(Pw[g * 68 + k0 + tg + 4]);
            uint32_t a3 = __float_as_uint(Pw[(g + 8) * 68 + k0 + tg + 4]);
            #pragma unroll
            for (int ni = 0; ni < 8; ni++) {
                uint32_t b0 = __float_as_uint(Vs[(k0 + tg) * 72 + ni * 8 + g]);
                uint32_t b1 = __float_as_uint(Vs[(k0 + tg + 4) * 72 + ni * 8 + g]);
                mma_tf32(o[ni][0], o[ni][1], o[ni][2], o[ni][3], a0, a1, a2, a3, b0, b1);
            }
        }
        __syncthreads();
    }

    const float inv0 = 1.0f / l0, inv1 = 1.0f / l1;
    float* dst0 = &ctx[((long)(b * SS + qg0)) * DD + h * DKK];
    float* dst1 = &ctx[((long)(b * SS + qg1)) * DD + h * DKK];
    #pragma unroll
    for (int ni = 0; ni < 8; ni++) {
        int cl = ni * 8 + 2 * tg;
        *(float2*)&dst0[cl] = make_float2(o[ni][0] * inv0, o[ni][1] * inv0);
        *(float2*)&dst1[cl] = make_float2(o[ni][2] * inv1, o[ni][3] * inv1);
    }
}

// ---------------- residual + LayerNorm (float4, 128 thr/row) --------------
__global__ __launch_bounds__(128) void ln_kernel(
    const float* __restrict__ X, const float* __restrict__ R,
    const float* __restrict__ g, const float* __restrict__ bta,
    float* __restrict__ out)
{
    const int row = blockIdx.x;
    const int t = threadIdx.x;
    const long rb = (long)row * DD;
    float4 a = *(const float4*)&X[rb + t * 4];
    float4 r = *(const float4*)&R[rb + t * 4];
    float4 xv = make_float4(a.x + r.x, a.y + r.y, a.z + r.z, a.w + r.w);

    __shared__ float red[4], red2[4];

    float s = xv.x + xv.y + xv.z + xv.w;
    #pragma unroll
    for (int o = 16; o; o >>= 1) s += __shfl_xor_sync(0xffffffffu, s, o);
    if ((t & 31) == 0) red[t >> 5] = s;
    __syncthreads();
    const float mu = (red[0] + red[1] + red[2] + red[3]) * (1.0f / DD);

    float4 d = make_float4(xv.x - mu, xv.y - mu, xv.z - mu, xv.w - mu);
    float s2 = d.x * d.x + d.y * d.y + d.z * d.z + d.w * d.w;
    #pragma unroll
    for (int o = 16; o; o >>= 1) s2 += __shfl_xor_sync(0xffffffffu, s2, o);
    if ((t & 31) == 0) red2[t >> 5] = s2;
    __syncthreads();
    const float rstd = rsqrtf((red2[0] + red2[1] + red2[2] + red2[3]) * (1.0f / DD) + 1e-5f);

    float4 gg = *(const float4*)&g[t * 4];
    float4 bb = *(const float4*)&bta[t * 4];
    float4 o4;
    o4.x = d.x * rstd * gg.x + bb.x;
    o4.y = d.y * rstd * gg.y + bb.y;
    o4.z = d.z * rstd * gg.z + bb.z;
    o4.w = d.w * rstd * gg.w + bb.w;
    *(float4*)&out[rb + t * 4] = o4;
}

// ---------------- launch ----------------
extern "C" void kernel_launch(void* const* d_in, const int* in_sizes, int n_in,
                              void* d_out, int out_size)
{
    const float* Q      = (const float*)d_in[0];
    const float* K      = (const float*)d_in[1];
    const float* V      = (const float*)d_in[2];
    const unsigned char* mask = (const unsigned char*)d_in[3];
    const float* W_q    = (const float*)d_in[4];
    const float* W_k    = (const float*)d_in[5];
    const float* W_v    = (const float*)d_in[6];
    const float* W_o    = (const float*)d_in[7];
    const float* lin1_w = (const float*)d_in[8];
    const float* lin1_b = (const float*)d_in[9];
    const float* lin2_w = (const float*)d_in[10];
    const float* lin2_b = (const float*)d_in[11];
    const float* ln_g   = (const float*)d_in[12];
    const float* ln_b   = (const float*)d_in[13];
    float* out = (float*)d_out;

    float *ctx, *att, *out1, *hid, *ffn, *Wr;
    cudaGetSymbolAddress((void**)&ctx, g_ctx);
    cudaGetSymbolAddress((void**)&att, g_att);
    cudaGetSymbolAddress((void**)&out1, g_out1);
    cudaGetSymbolAddress((void**)&hid, g_hid);
    cudaGetSymbolAddress((void**)&ffn, g_ffn);
    cudaGetSymbolAddress((void**)&Wr,  g_Wr);

    cudaFuncSetAttribute(gemm_qkv_kernel,
                         cudaFuncAttributeMaxDynamicSharedMemorySize, GEMM_SMEM_BYTES);
    cudaFuncSetAttribute(gemm_kernel<EPI_PLAIN>,
                         cudaFuncAttributeMaxDynamicSharedMemorySize, GEMM_SMEM_BYTES);
    cudaFuncSetAttribute(gemm_kernel<EPI_BIAS>,
                         cudaFuncAttributeMaxDynamicSharedMemorySize, GEMM_SMEM_BYTES);
    cudaFuncSetAttribute(gemm_kernel<EPI_BIASGELU>,
                         cudaFuncAttributeMaxDynamicSharedMemorySize, GEMM_SMEM_BYTES);
    cudaFuncSetAttribute(flash_tc_kernel,
                         cudaFuncAttributeMaxDynamicSharedMemorySize, FLASH_SMEM_BYTES);

    // 0) pre-round all weights (rna -> kills tf32 truncation bias)
    wround_kernel<<<dim3(256, 6), 256>>>(W_q, W_k, W_v, W_o, lin1_w, lin2_w, Wr);

    dim3 ggrid(DD / 128, MROWS / 128);         // (4, 128)
    const float invT = 1.0f / (8.0f + 1e-6f);  // 1/(sqrt(DK)+eps), folded into Q proj

    // 1) fused QKV projections (rounded head-layout outputs)
    gemm_qkv_kernel<<<dim3(4, 128, 3), 256, GEMM_SMEM_BYTES>>>(Q, K, V, Wr, invT);

    // 2) attention
    flash_tc_kernel<<<dim3(SS / 64, HH, BB), 128, FLASH_SMEM_BYTES>>>(mask, ctx);

    // 3) output projection + residual LN
    gemm_kernel<EPI_PLAIN><<<ggrid, 256, GEMM_SMEM_BYTES>>>(ctx, Wr + 3L * WSZ, nullptr, att, 1.0f);
    ln_kernel<<<MROWS, 128>>>(att, Q, ln_g, ln_b, out1);

    // 4) FFN
    gemm_kernel<EPI_BIASGELU><<<ggrid, 256, GEMM_SMEM_BYTES>>>(out1, Wr + 4L * WSZ, lin1_b, hid, 1.0f);
    gemm_kernel<EPI_BIAS><<<ggrid, 256, GEMM_SMEM_BYTES>>>(hid, Wr + 5L * WSZ, lin2_b, ffn, 1.0f);
    ln_kernel<<<MROWS, 128>>>(ffn, out1, ln_g, ln_b, out);
}

// round 14
// speedup vs baseline: 4.6490x; 1.0552x over previous
#include <cuda_runtime.h>
#include <cuda_bf16.h>
#include <cstdint>

// Problem constants
#define BB 16
#define SS 1024
#define DD 512
#define HH 8
#define DKK 64
#define MROWS (BB*SS)          // 16384
#define ELEMS (MROWS*DD)       // 8388608
#define WSZ (DD*DD)            // 262144

// ---------------- scratch buffers (no allocation allowed) ----------------
__device__ float g_Qh[ELEMS];   // [B,H,S,DK]  (tf32-rounded)
__device__ float g_Kh[ELEMS];
__device__ float g_Vh[ELEMS];
__device__ float g_ctx[ELEMS];  // [B*S, D]
__device__ float g_att[ELEMS];  // ctx @ W_o
__device__ float g_out1[ELEMS]; // after first LN
__device__ float g_hid[ELEMS];  // gelu(out1 @ lin1 + b1) (tf32-rounded)
__device__ float g_ffn[ELEMS];  // hid @ lin2 + b2
__device__ float g_Wr[6 * WSZ]; // tf32-rounded weights, original [k][n] layout

// ---------------- helpers ----------------
__device__ __forceinline__ float gelu_tanh_f(float x) {
    float x3 = x * x * x;
    return 0.5f * x * (1.0f + tanhf(0.7978845608028654f * (x + 0.044715f * x3)));
}

__device__ __forceinline__ uint32_t cvt_tf32(float x) {
    uint32_t u;
    asm("cvt.rna.tf32.f32 %0, %1;" : "=r"(u) : "f"(x));
    return u;
}
__device__ __forceinline__ float rna_tf32f(float x) {
    return __uint_as_float(cvt_tf32(x));
}

__device__ __forceinline__ void mma_tf32(
    float& d0, float& d1, float& d2, float& d3,
    uint32_t a0, uint32_t a1, uint32_t a2, uint32_t a3,
    uint32_t b0, uint32_t b1)
{
    asm volatile(
        "mma.sync.aligned.m16n8k8.row.col.f32.tf32.tf32.f32 "
        "{%0,%1,%2,%3}, {%4,%5,%6,%7}, {%8,%9}, {%0,%1,%2,%3};\n"
        : "+f"(d0), "+f"(d1), "+f"(d2), "+f"(d3)
        : "r"(a0), "r"(a1), "r"(a2), "r"(a3), "r"(b0), "r"(b1));
}

__device__ __forceinline__ uint32_t smem_u32(const void* p) {
    return (uint32_t)__cvta_generic_to_shared(p);
}
#define CP_ASYNC16(dst, src) \
    asm volatile("cp.async.cg.shared.global [%0], [%1], 16;\n" :: "r"(dst), "l"(src))
#define CP_COMMIT() asm volatile("cp.async.commit_group;\n")
#define CP_WAIT0()  asm volatile("cp.async.wait_group 0;\n")

// ============ weight rna pre-round (layout preserved [k][n]) ==============
__global__ __launch_bounds__(256) void wround_kernel(
    const float* __restrict__ W0, const float* __restrict__ W1,
    const float* __restrict__ W2, const float* __restrict__ W3,
    const float* __restrict__ W4, const float* __restrict__ W5,
    float* __restrict__ out)
{
    const float* Ws[6] = {W0, W1, W2, W3, W4, W5};
    const int z = blockIdx.y;
    const int idx = blockIdx.x * 256 + threadIdx.x;   // float4 index, 65536/matrix
    float4 v = ((const float4*)Ws[z])[idx];
    v.x = rna_tf32f(v.x); v.y = rna_tf32f(v.y);
    v.z = rna_tf32f(v.z); v.w = rna_tf32f(v.w);
    ((float4*)(out + (long)z * WSZ))[idx] = v;
}

// ================= TF32 GEMM 128x128x32, 4 warps x (64x64) warp tile ======
// 128 threads; per K=8 step each warp: 16 A-frag LDS + 16 B-frag LDS -> 32 MMA.
// As row-major [m][k] pad 36 (rna at STS); Bs [k][n] pad 136 (pre-rounded
// weights via cp.async). Barrier at END of iter; prefetch at TOP (race-free:
// writes to buf^1 occur strictly after the barrier that fenced its readers).
#define TBK 32
#define A_STAGE (128*36)     // 4608 floats
#define B_STAGE (TBK*136)    // 4352 floats
#define GEMM_SMEM_BYTES (2*(A_STAGE + B_STAGE)*4)   // 71680

enum { EPI_QKV = 0, EPI_PLAIN = 1, EPI_BIAS = 2, EPI_BIASGELU = 3 };

template <int EPI>
__device__ __forceinline__ void gemm_body(
    const float* __restrict__ A,     // [16384, 512] fp32
    const float* __restrict__ Bw,    // [512, 512] fp32, pre-rounded tf32
    const float* __restrict__ bias,  // [512] or null
    float* __restrict__ C, float scale)
{
    extern __shared__ float gsm[];

    const int tid  = threadIdx.x;     // 0..127
    const int lane = tid & 31;
    const int warp = tid >> 5;        // 0..3
    const int warpM = warp >> 1;      // 0..1
    const int warpN = warp & 1;       // 0..1
    const int g  = lane >> 2;         // 0..7
    const int tg = lane & 3;          // 0..3

    const int mBase = warpM * 64;
    const int nBase = warpN * 64;

    const long rowBlock = (long)blockIdx.y * 128;
    const int  colBlock = blockIdx.x * 128;

    // loader mapping (1024 float4 per tile, 8 per thread)
    const int lrA = tid >> 3;             // 0..15 -> rows lrA + 16*i
    const int lcA = (tid & 7) << 2;       // 0..28
    const int lrB = tid >> 5;             // 0..3  -> k-rows lrB + 4*i
    const int lcB = (tid & 31) << 2;      // 0..124

    float acc[4][8][4];
    #pragma unroll
    for (int i = 0; i < 4; i++)
        #pragma unroll
        for (int j = 0; j < 8; j++)
            #pragma unroll
            for (int c = 0; c < 4; c++) acc[i][j][c] = 0.0f;

    const int nt = 512 / TBK;   // 16

    auto issueB = [&](int kt, int stage) {
        float* BsS = gsm + 2 * A_STAGE + stage * B_STAGE;
        #pragma unroll
        for (int i = 0; i < 8; i++) {
            int r = lrB + 4 * i;
            CP_ASYNC16(smem_u32(&BsS[r * 136 + lcB]),
                       Bw + (long)(kt + r) * 512 + colBlock + lcB);
        }
    };
    auto ldA = [&](int kt, float4* ar) {
        #pragma unroll
        for (int i = 0; i < 8; i++) {
            int r = lrA + 16 * i;
            ar[i] = *(const float4*)(A + (rowBlock + r) * 512 + kt + lcA);
        }
    };
    auto stA = [&](int stage, const float4* ar) {
        float* AsS = gsm + stage * A_STAGE;
        #pragma unroll
        for (int i = 0; i < 8; i++) {
            int r = lrA + 16 * i;
            float4 v = ar[i];
            v.x = rna_tf32f(v.x); v.y = rna_tf32f(v.y);
            v.z = rna_tf32f(v.z); v.w = rna_tf32f(v.w);
            *(float4*)&AsS[r * 36 + lcA] = v;
        }
    };

    // ---- prologue: tile 0 into buffer 0, published to all warps ----
    {
        float4 ar[8];
        issueB(0, 0);
        CP_COMMIT();
        ldA(0, ar);
        stA(0, ar);
        CP_WAIT0();
        __syncthreads();
    }

    int buf = 0;
    for (int it = 0; it < nt; it++) {
        float4 ar[8];
        const bool pre = (it + 1 < nt);
        if (pre) {
            issueB((it + 1) * TBK, buf ^ 1);   // safe: readers fenced by prior barrier
            CP_COMMIT();
            ldA((it + 1) * TBK, ar);           // LDG overlaps MMA below
        }

        const float* AsS = gsm + buf * A_STAGE;
        const float* BsS = gsm + 2 * A_STAGE + buf * B_STAGE;

        #pragma unroll
        for (int kk = 0; kk < 4; kk++) {
            const int k0 = kk * 8;
            uint32_t af[4][4];
            #pragma unroll
            for (int mi = 0; mi < 4; mi++) {
                int m = mBase + mi * 16 + g;
                af[mi][0] = __float_as_uint(AsS[m * 36 + k0 + tg]);
                af[mi][1] = __float_as_uint(AsS[(m + 8) * 36 + k0 + tg]);
                af[mi][2] = __float_as_uint(AsS[m * 36 + k0 + tg + 4]);
                af[mi][3] = __float_as_uint(AsS[(m + 8) * 36 + k0 + tg + 4]);
            }
            uint32_t bf[8][2];
            #pragma unroll
            for (int ni = 0; ni < 8; ni++) {
                int n = nBase + ni * 8 + g;
                bf[ni][0] = __float_as_uint(BsS[(k0 + tg) * 136 + n]);
                bf[ni][1] = __float_as_uint(BsS[(k0 + tg + 4) * 136 + n]);
            }
            #pragma unroll
            for (int mi = 0; mi < 4; mi++)
                #pragma unroll
                for (int ni = 0; ni < 8; ni++)
                    mma_tf32(acc[mi][ni][0], acc[mi][ni][1], acc[mi][ni][2], acc[mi][ni][3],
                             af[mi][0], af[mi][1], af[mi][2], af[mi][3],
                             bf[ni][0], bf[ni][1]);
        }

        if (pre) {
            stA(buf ^ 1, ar);   // writes buf^1: readers fenced by prior barrier
            CP_WAIT0();         // B(it+1) landed in smem
        }
        __syncthreads();        // close iter: publish tile it+1, fence reads of buf
        buf ^= 1;
    }

    // ---- epilogue ----
    #pragma unroll
    for (int mi = 0; mi < 4; mi++) {
        #pragma unroll
        for (int ri = 0; ri < 2; ri++) {
            int m = (int)rowBlock + mBase + mi * 16 + g + ri * 8;
            #pragma unroll
            for (int ni = 0; ni < 8; ni++) {
                int n = colBlock + nBase + ni * 8 + tg * 2;
                float v0 = acc[mi][ni][ri * 2 + 0];
                float v1 = acc[mi][ni][ri * 2 + 1];
                if (EPI == EPI_QKV) {
                    // store rna-rounded so flash operands are exact tf32
                    int b = m >> 10, s = m & 1023;
                    int h = n >> 6, dk = n & 63;
                    float2 o;
                    o.x = rna_tf32f(v0 * scale);
                    o.y = rna_tf32f(v1 * scale);
                    *(float2*)&C[(((((long)b * HH + h) << 10) + s) << 6) + dk] = o;
                } else if (EPI == EPI_PLAIN) {
                    float2 o; o.x = v0; o.y = v1;
                    *(float2*)&C[(long)m * DD + n] = o;
                } else if (EPI == EPI_BIAS) {
                    float2 o; o.x = v0 + bias[n]; o.y = v1 + bias[n + 1];
                    *(float2*)&C[(long)m * DD + n] = o;
                } else {  // EPI_BIASGELU -> hid (rounded: consumed only by lin2)
                    float2 o;
                    o.x = rna_tf32f(gelu_tanh_f(v0 + bias[n]));
                    o.y = rna_tf32f(gelu_tanh_f(v1 + bias[n + 1]));
                    *(float2*)&C[(long)m * DD + n] = o;
                }
            }
        }
    }
}

template <int EPI>
__global__ __launch_bounds__(128, 2) void gemm_kernel(
    const float* __restrict__ A, const float* __restrict__ Bw,
    const float* __restrict__ bias, float* __restrict__ C, float scale)
{
    gemm_body<EPI>(A, Bw, bias, C, scale);
}

// fused QKV: blockIdx.z selects (input, weight, output, scale)
__global__ __launch_bounds__(128, 2) void gemm_qkv_kernel(
    const float* __restrict__ Q, const float* __restrict__ K,
    const float* __restrict__ V, const float* __restrict__ Wr,
    float invT)
{
    const int z = blockIdx.z;
    const float* A = (z == 0) ? Q : (z == 1) ? K : V;
    float* C = (z == 0) ? g_Qh : (z == 1) ? g_Kh : g_Vh;
    gemm_body<EPI_QKV>(A, Wr + (long)z * WSZ, nullptr, C,
                       (z == 0) ? invT : 1.0f);
}

// ================= Tensor-core flash attention ============================
// Br=64 (4 warps x m16), Bc=64; double-buffered K/V/mask via cp.async with
// prefetch-at-top / barrier-at-end ordering (same proof as the GEMM loop).
// smem (floats): 2 stages of [Ks 64x68 | Vs 64x72 | mask 16] = 8976 each,
// then P 4x[16][68].
#define FL_STAGE 8976
#define FL_P (2*FL_STAGE)                        // 17952
#define FLASH_SMEM_BYTES ((FL_P + 4*1088) * 4)   // 89216

__global__ __launch_bounds__(128) void flash_tc_kernel(
    const unsigned char* __restrict__ mask, float* __restrict__ ctx)
{
    extern __shared__ float fsm[];

    const int t = threadIdx.x;
    const int lane = t & 31, warp = t >> 5;
    const int g = lane >> 2, tg = lane & 3;
    const int qt = blockIdx.x;
    const int h = blockIdx.y;
    const int b = blockIdx.z;
    const long base = ((long)(b * HH + h)) << 16;
    const int q0 = qt * 64;
    const int rowg = warp * 16 + g;
    const int qg0 = q0 + rowg;
    const int qg1 = qg0 + 8;
    float* Pw = fsm + FL_P + warp * (16 * 68);

    // ---- Q fragments via stage-0 Ks area (overwritten later) ----
    {
        float* Ks0 = fsm;
        #pragma unroll
        for (int i = 0; i < 8; i++) {
            int idx = t + 128 * i;
            int r = idx >> 4, c = (idx & 15) << 2;
            *(float4*)&Ks0[r * 68 + c] = *(const float4*)&g_Qh[base + (long)(q0 + r) * 64 + c];
        }
    }
    __syncthreads();
    uint32_t qf[8][4];
    {
        float* Ks0 = fsm;
        #pragma unroll
        for (int kk = 0; kk < 8; kk++) {
            int k0 = kk * 8;
            qf[kk][0] = __float_as_uint(Ks0[rowg * 68 + k0 + tg]);
            qf[kk][1] = __float_as_uint(Ks0[(rowg + 8) * 68 + k0 + tg]);
            qf[kk][2] = __float_as_uint(Ks0[rowg * 68 + k0 + tg + 4]);
            qf[kk][3] = __float_as_uint(Ks0[(rowg + 8) * 68 + k0 + tg + 4]);
        }
    }
    __syncthreads();

    auto prefetch = [&](int kb, int st) {
        float* S = fsm + st * FL_STAGE;
        uint32_t Ksu = smem_u32(S);
        uint32_t Vsu = smem_u32(S + 4352);
        #pragma unroll
        for (int i = 0; i < 8; i++) {
            int idx = t + 128 * i;
            int r = idx >> 4, c = (idx & 15) << 2;
            CP_ASYNC16(Ksu + (uint32_t)(r * 68 + c) * 4, &g_Kh[base + (long)(kb + r) * 64 + c]);
            CP_ASYNC16(Vsu + (uint32_t)(r * 72 + c) * 4, &g_Vh[base + (long)(kb + r) * 64 + c]);
        }
        if (t < 4) {
            uint32_t Mu = smem_u32(S + 8960);
            CP_ASYNC16(Mu + t * 16, mask + (long)b * SS + kb + t * 16);
        }
    };

    float o[8][4];
    #pragma unroll
    for (int i = 0; i < 8; i++)
        #pragma unroll
        for (int j = 0; j < 4; j++) o[i][j] = 0.0f;
    float m0 = -1e30f, m1 = -1e30f, l0 = 0.0f, l1 = 0.0f;

    const int ntiles = qt + 1;

    // prologue: tile 0 -> stage 0
    prefetch(0, 0);
    CP_COMMIT();
    CP_WAIT0();
    __syncthreads();

    for (int kt = 0; kt < ntiles; kt++) {
        const int kb = kt * 64;
        const int st = kt & 1;
        const bool pre = (kt + 1 < ntiles);
        if (pre) {
            prefetch(kb + 64, st ^ 1);   // safe: readers fenced by prior barrier
            CP_COMMIT();
        }

        const float* Ks = fsm + st * FL_STAGE;
        const float* Vs = Ks + 4352;
        const unsigned char* Msk = (const unsigned char*)(Ks + 8960);

        // ---- S = Q . K^T ----
        float s[8][4];
        #pragma unroll
        for (int i = 0; i < 8; i++)
            #pragma unroll
            for (int j = 0; j < 4; j++) s[i][j] = 0.0f;
        #pragma unroll
        for (int kk = 0; kk < 8; kk++) {
            int k0 = kk * 8;
            #pragma unroll
            for (int ni = 0; ni < 8; ni++) {
                uint32_t b0 = __float_as_uint(Ks[(ni * 8 + g) * 68 + k0 + tg]);
                uint32_t b1 = __float_as_uint(Ks[(ni * 8 + g) * 68 + k0 + tg + 4]);
                mma_tf32(s[ni][0], s[ni][1], s[ni][2], s[ni][3],
                         qf[kk][0], qf[kk][1], qf[kk][2], qf[kk][3], b0, b1);
            }
        }

        // ---- mask + row max ----
        float tmax0 = -1e30f, tmax1 = -1e30f;
        if (kb + 64 > q0) {
            // diagonal tile: causal + pad
            #pragma unroll
            for (int ni = 0; ni < 8; ni++) {
                int cl = ni * 8 + 2 * tg;
                int c0g = kb + cl, c1g = c0g + 1;
                bool pm0 = Msk[cl] != 0, pm1 = Msk[cl + 1] != 0;
                if (c0g > qg0 || pm0) s[ni][0] = -1e30f;
                if (c1g > qg0 || pm1) s[ni][1] = -1e30f;
                if (c0g > qg1 || pm0) s[ni][2] = -1e30f;
                if (c1g > qg1 || pm1) s[ni][3] = -1e30f;
                tmax0 = fmaxf(tmax0, fmaxf(s[ni][0], s[ni][1]));
                tmax1 = fmaxf(tmax1, fmaxf(s[ni][2], s[ni][3]));
            }
        } else {
            // strictly-below-diagonal: pad mask only
            #pragma unroll
            for (int ni = 0; ni < 8; ni++) {
                int cl = ni * 8 + 2 * tg;
                bool pm0 = Msk[cl] != 0, pm1 = Msk[cl + 1] != 0;
                if (pm0) { s[ni][0] = -1e30f; s[ni][2] = -1e30f; }
                if (pm1) { s[ni][1] = -1e30f; s[ni][3] = -1e30f; }
                tmax0 = fmaxf(tmax0, fmaxf(s[ni][0], s[ni][1]));
                tmax1 = fmaxf(tmax1, fmaxf(s[ni][2], s[ni][3]));
            }
        }
        #pragma unroll
        for (int off = 1; off <= 2; off <<= 1) {
            tmax0 = fmaxf(tmax0, __shfl_xor_sync(0xffffffffu, tmax0, off));
            tmax1 = fmaxf(tmax1, __shfl_xor_sync(0xffffffffu, tmax1, off));
        }

        float mnew0 = fmaxf(m0, tmax0), mnew1 = fmaxf(m1, tmax1);
        float corr0 = __expf(m0 - mnew0), corr1 = __expf(m1 - mnew1);

        // P = rna(exp(S-m)) (rounded values feed BOTH l and P.V)
        float ls0 = 0.0f, ls1 = 0.0f;
        #pragma unroll
        for (int ni = 0; ni < 8; ni++) {
            float p00 = rna_tf32f(__expf(s[ni][0] - mnew0));
            float p01 = rna_tf32f(__expf(s[ni][1] - mnew0));
            float p10 = rna_tf32f(__expf(s[ni][2] - mnew1));
            float p11 = rna_tf32f(__expf(s[ni][3] - mnew1));
            ls0 += p00 + p01;
            ls1 += p10 + p11;
            int cl = ni * 8 + 2 * tg;
            *(float2*)&Pw[g * 68 + cl] = make_float2(p00, p01);
            *(float2*)&Pw[(g + 8) * 68 + cl] = make_float2(p10, p11);
        }
        #pragma unroll
        for (int off = 1; off <= 2; off <<= 1) {
            ls0 += __shfl_xor_sync(0xffffffffu, ls0, off);
            ls1 += __shfl_xor_sync(0xffffffffu, ls1, off);
        }
        l0 = l0 * corr0 + ls0;
        l1 = l1 * corr1 + ls1;
        m0 = mnew0; m1 = mnew1;

        #pragma unroll
        for (int ni = 0; ni < 8; ni++) {
            o[ni][0] *= corr0; o[ni][1] *= corr0;
            o[ni][2] *= corr1; o[ni][3] *= corr1;
        }
        __syncwarp();   // Pw visible within warp

        // ---- O += P . V ----
        #pragma unroll
        for (int kk = 0; kk < 8; kk++) {
            int k0 = kk * 8;
            uint32_t a0 = __float_as_uint(Pw[g * 68 + k0 + tg]);
            uint32_t a1 = __float_as_uint(Pw[(g + 8) * 68 + k0 + tg]);
            uint32_t a2 = __float_as_uint(Pw[g * 68 + k0 + tg + 4]);
            uint32_t a3 = __float_as_uint(Pw[(g + 8) * 68 + k0 + tg + 4]);
            #pragma unroll
            for (int ni = 0; ni < 8; ni++) {
                uint32_t b0 = __float_as_uint(Vs[(k0 + tg) * 72 + ni * 8 + g]);
                uint32_t b1 = __float_as_uint(Vs[(k0 + tg + 4) * 72 + ni * 8 + g]);
                mma_tf32(o[ni][0], o[ni][1], o[ni][2], o[ni][3], a0, a1, a2, a3, b0, b1);
            }
        }

        if (pre) CP_WAIT0();   // next tile landed (overlapped with compute)
        __syncthreads();       // close iter: publish next tile, fence reads of st
    }

    const float inv0 = 1.0f / l0, inv1 = 1.0f / l1;
    float* dst0 = &ctx[((long)(b * SS + qg0)) * DD + h * DKK];
    float* dst1 = &ctx[((long)(b * SS + qg1)) * DD + h * DKK];
    #pragma unroll
    for (int ni = 0; ni < 8; ni++) {
        int cl = ni * 8 + 2 * tg;
        *(float2*)&dst0[cl] = make_float2(o[ni][0] * inv0, o[ni][1] * inv0);
        *(float2*)&dst1[cl] = make_float2(o[ni][2] * inv1, o[ni][3] * inv1);
    }
}

// ---------------- residual + LayerNorm (float4, 128 thr/row) --------------
__global__ __launch_bounds__(128) void ln_kernel(
    const float* __restrict__ X, const float* __restrict__ R,
    const float* __restrict__ g, const float* __restrict__ bta,
    float* __restrict__ out)
{
    const int row = blockIdx.x;
    const int t = threadIdx.x;
    const long rb = (long)row * DD;
    float4 a = *(const float4*)&X[rb + t * 4];
    float4 r = *(const float4*)&R[rb + t * 4];
    float4 xv = make_float4(a.x + r.x, a.y + r.y, a.z + r.z, a.w + r.w);

    __shared__ float red[4], red2[4];

    float s = xv.x + xv.y + xv.z + xv.w;
    #pragma unroll
    for (int o = 16; o; o >>= 1) s += __shfl_xor_sync(0xffffffffu, s, o);
    if ((t & 31) == 0) red[t >> 5] = s;
    __syncthreads();
    const float mu = (red[0] + red[1] + red[2] + red[3]) * (1.0f / DD);

    float4 d = make_float4(xv.x - mu, xv.y - mu, xv.z - mu, xv.w - mu);
    float s2 = d.x * d.x + d.y * d.y + d.z * d.z + d.w * d.w;
    #pragma unroll
    for (int o = 16; o; o >>= 1) s2 += __shfl_xor_sync(0xffffffffu, s2, o);
    if ((t & 31) == 0) red2[t >> 5] = s2;
    __syncthreads();
    const float rstd = rsqrtf((red2[0] + red2[1] + red2[2] + red2[3]) * (1.0f / DD) + 1e-5f);

    float4 gg = *(const float4*)&g[t * 4];
    float4 bb = *(const float4*)&bta[t * 4];
    float4 o4;
    o4.x = d.x * rstd * gg.x + bb.x;
    o4.y = d.y * rstd * gg.y + bb.y;
    o4.z = d.z * rstd * gg.z + bb.z;
    o4.w = d.w * rstd * gg.w + bb.w;
    *(float4*)&out[rb + t * 4] = o4;
}

// ---------------- launch ----------------
extern "C" void kernel_launch(void* const* d_in, const int* in_sizes, int n_in,
                              void* d_out, int out_size)
{
    const float* Q      = (const float*)d_in[0];
    const float* K      = (const float*)d_in[1];
    const float* V      = (const float*)d_in[2];
    const unsigned char* mask = (const unsigned char*)d_in[3];
    const float* W_q    = (const float*)d_in[4];
    const float* W_k    = (const float*)d_in[5];
    const float* W_v    = (const float*)d_in[6];
    const float* W_o    = (const float*)d_in[7];
    const float* lin1_w = (const float*)d_in[8];
    const float* lin1_b = (const float*)d_in[9];
    const float* lin2_w = (const float*)d_in[10];
    const float* lin2_b = (const float*)d_in[11];
    const float* ln_g   = (const float*)d_in[12];
    const float* ln_b   = (const float*)d_in[13];
    float* out = (float*)d_out;

    float *ctx, *att, *out1, *hid, *ffn, *Wr;
    cudaGetSymbolAddress((void**)&ctx, g_ctx);
    cudaGetSymbolAddress((void**)&att, g_att);
    cudaGetSymbolAddress((void**)&out1, g_out1);
    cudaGetSymbolAddress((void**)&hid, g_hid);
    cudaGetSymbolAddress((void**)&ffn, g_ffn);
    cudaGetSymbolAddress((void**)&Wr,  g_Wr);

    cudaFuncSetAttribute(gemm_qkv_kernel,
                         cudaFuncAttributeMaxDynamicSharedMemorySize, GEMM_SMEM_BYTES);
    cudaFuncSetAttribute(gemm_kernel<EPI_PLAIN>,
                         cudaFuncAttributeMaxDynamicSharedMemorySize, GEMM_SMEM_BYTES);
    cudaFuncSetAttribute(gemm_kernel<EPI_BIAS>,
                         cudaFuncAttributeMaxDynamicSharedMemorySize, GEMM_SMEM_BYTES);
    cudaFuncSetAttribute(gemm_kernel<EPI_BIASGELU>,
                         cudaFuncAttributeMaxDynamicSharedMemorySize, GEMM_SMEM_BYTES);
    cudaFuncSetAttribute(flash_tc_kernel,
                         cudaFuncAttributeMaxDynamicSharedMemorySize, FLASH_SMEM_BYTES);

    // 0) pre-round all weights (rna -> kills tf32 truncation bias)
    wround_kernel<<<dim3(256, 6), 256>>>(W_q, W_k, W_v, W_o, lin1_w, lin2_w, Wr);

    dim3 ggrid(DD / 128, MROWS / 128);         // (4, 128)
    const float invT = 1.0f / (8.0f + 1e-6f);  // 1/(sqrt(DK)+eps), folded into Q proj

    // 1) fused QKV projections (rounded head-layout outputs)
    gemm_qkv_kernel<<<dim3(4, 128, 3), 128, GEMM_SMEM_BYTES>>>(Q, K, V, Wr, invT);

    // 2) attention
    flash_tc_kernel<<<dim3(SS / 64, HH, BB), 128, FLASH_SMEM_BYTES>>>(mask, ctx);

    // 3) output projection + residual LN
    gemm_kernel<EPI_PLAIN><<<ggrid, 128, GEMM_SMEM_BYTES>>>(ctx, Wr + 3L * WSZ, nullptr, att, 1.0f);
    ln_kernel<<<MROWS, 128>>>(att, Q, ln_g, ln_b, out1);

    // 4) FFN
    gemm_kernel<EPI_BIASGELU><<<ggrid, 128, GEMM_SMEM_BYTES>>>(out1, Wr + 4L * WSZ, lin1_b, hid, 1.0f);
    gemm_kernel<EPI_BIAS><<<ggrid, 128, GEMM_SMEM_BYTES>>>(hid, Wr + 5L * WSZ, lin2_b, ffn, 1.0f);
    ln_kernel<<<MROWS, 128>>>(ffn, out1, ln_g, ln_b, out);
}